// round 10
// baseline (speedup 1.0000x reference)
#include <cuda_runtime.h>
#include <math.h>
#include <stdint.h>

#define NN      32768
#define NHOPS   6
#define NFEAT_  512
#define NSSF_   256
#define NCLASS_ 40
#define NEG_    0.2f
#define COS_EPS_ 1e-6f

// output layout (flattened tuple, element offsets)
#define OUT_OFF   0
#define SSFN_OFF  (NN*NCLASS_)                    // 1310720
#define Z_OFF     (SSFN_OFF + NSSF_*NCLASS_)      // 1320960
#define LOSS_OFF  (Z_OFF + NN*NSSF_)              // 9709568
#define SIGMA_OFF (LOSS_OFF + NN*NCLASS_)         // 11020288

// scratch (static device globals — no runtime allocation)
__device__ float g_z1[(long)NN * 512];
__device__ float g_zsq[NN];
__device__ float g_zn[NN];
__device__ float g_csq[NCLASS_];
__device__ float g_cn[NCLASS_];
__device__ uint32_t g_Wp_tf[512 * 512];   // W_pre pre-converted to tf32
__device__ uint32_t g_Wq_tf[256 * 512];   // W_post pre-converted to tf32

// ---------------------------------------------------------------------------
// helpers
// ---------------------------------------------------------------------------
__device__ __forceinline__ uint32_t f2tf(float x) {
    uint32_t y;
    asm("cvt.rna.tf32.f32 %0, %1;" : "=r"(y) : "f"(x));
    return y;
}
__device__ __forceinline__ void mma8(float c[4], const uint32_t a[4],
                                     const uint32_t b[2]) {
    asm volatile(
        "mma.sync.aligned.m16n8k8.row.col.f32.tf32.tf32.f32 "
        "{%0,%1,%2,%3}, {%4,%5,%6,%7}, {%8,%9}, {%0,%1,%2,%3};\n"
        : "+f"(c[0]), "+f"(c[1]), "+f"(c[2]), "+f"(c[3])
        : "r"(a[0]), "r"(a[1]), "r"(a[2]), "r"(a[3]), "r"(b[0]), "r"(b[1]));
}
__device__ __forceinline__ uint32_t smem_u32p(const void* p) {
    uint32_t a;
    asm("{ .reg .u64 t; cvta.to.shared.u64 t, %1; cvt.u32.u64 %0, t; }"
        : "=r"(a) : "l"(p));
    return a;
}
__device__ __forceinline__ void cp16(uint32_t saddr, const void* g) {
    asm volatile("cp.async.ca.shared.global [%0], [%1], 16;"
                 :: "r"(saddr), "l"(g));
}
#define CP_COMMIT() asm volatile("cp.async.commit_group;")
#define CP_WAIT0()  asm volatile("cp.async.wait_group 0;")

// ---------------------------------------------------------------------------
// Kw: weight tf32 pre-convert (blocks 0..1535) + K0 ssf work (block 1536,
// runs concurrently instead of serializing as its own 1-block launch).
// ---------------------------------------------------------------------------
__global__ void __launch_bounds__(256) smn_wcvt_ssf(
    const float* __restrict__ Wp, const float* __restrict__ Wq,
    const float* __restrict__ ssf, const float* __restrict__ sigma,
    float* __restrict__ dout)
{
    __shared__ float fbuf[NSSF_ * NCLASS_];
    __shared__ int   cnt_s[256];
    const int tid = threadIdx.x;

    if (blockIdx.x < 1536) {
        int i = blockIdx.x * 256 + tid;
        if (i < 512 * 512) {
            g_Wp_tf[i] = f2tf(Wp[i]);
        } else {
            int j = i - 512 * 512;
            if (j < 256 * 512) g_Wq_tf[j] = f2tf(Wq[j]);
        }
        return;
    }

    // ---- K0: exact threshold select + ssf_norm + column norms + sigma ----
    unsigned* keys = reinterpret_cast<unsigned*>(fbuf);
    for (int i = tid; i < NSSF_ * NCLASS_; i += 256)
        keys[i] = __float_as_uint(fabsf(ssf[i]));
    __syncthreads();

    unsigned lo = 0u, hi = 0x7f800000u;
    while (lo < hi) {
        unsigned mid = (lo + hi) >> 1;
        int c = 0;
        for (int i = tid; i < NSSF_ * NCLASS_; i += 256) c += (keys[i] <= mid);
        cnt_s[tid] = c;
        __syncthreads();
        for (int s = 128; s > 0; s >>= 1) {
            if (tid < s) cnt_s[tid] += cnt_s[tid + s];
            __syncthreads();
        }
        int total = cnt_s[0];
        __syncthreads();
        if (total >= 5121) hi = mid; else lo = mid + 1;
    }
    const float thr = __uint_as_float(lo);

    float row[NCLASS_];
    float rs = 0.f;
    const float* srow = ssf + tid * NCLASS_;
#pragma unroll
    for (int j = 0; j < NCLASS_; j++) {
        float v = srow[j];
        v = (fabsf(v) >= thr) ? v : 0.f;
        row[j] = v;
        rs += fabsf(v);
    }
    const float inv = 1.f / fmaxf(rs, 1e-12f);
#pragma unroll
    for (int j = 0; j < NCLASS_; j++) {
        float v = row[j] * inv;
        dout[SSFN_OFF + tid * NCLASS_ + j] = v;
        fbuf[tid * NCLASS_ + j] = v;
    }
    __syncthreads();

    if (tid < NCLASS_) {
        float c2 = 0.f;
        for (int i = 0; i < NSSF_; i++) {
            float v = fbuf[i * NCLASS_ + tid];
            c2 += v * v;
        }
        g_csq[tid] = c2;
        g_cn[tid]  = fmaxf(sqrtf(c2), COS_EPS_);
    }
    if (tid < 2) dout[SIGMA_OFF + tid] = sigma[tid];
}

// ---------------------------------------------------------------------------
// K1 (tf32 mma, 384 threads / 12 warps / warp tile 32x32, 2 blocks/SM =
// 24 warps/SM): h = lrelu(x @ W_pre^T + b) -> hop softmax.
// Block 96x128. Dynamic smem: atts[768] | As[2][96][36] | Bs[2][128][36]
// = 67584 B (unchanged; co-residency preserved, warps +50%).
// ---------------------------------------------------------------------------
__global__ void __launch_bounds__(384, 2) smn_k1_tc(
    const float* __restrict__ x,
    const float* __restrict__ bp, const float* __restrict__ att)
{
    extern __shared__ uint32_t dynsmem[];
    float*    atts = (float*)dynsmem;         // 768
    uint32_t* As   = dynsmem + 768;           // 2 * 96*36
    uint32_t* Bs   = As + 2 * 96 * 36;        // 2 * 128*36

    const int tid  = threadIdx.x;
    const int lane = tid & 31, warp = tid >> 5;        // 12 warps
    const int warpM = warp >> 2, warpN = warp & 3;     // 3 x 4
    const int g = lane >> 2, t = lane & 3;
    const int node0 = blockIdx.y * 16;
    const int col0  = blockIdx.x * 128;
    const long row0 = (long)node0 * NHOPS;

    for (int i = tid; i < 768; i += 384)
        atts[i] = att[2 * blockIdx.x * 384 + i];

    // A staging: 96 rows x 8 float4 groups = 768 slots, 2 per thread
    const int ar[2] = { (tid) >> 3, (tid + 384) >> 3 };
    const int ac    = (tid & 7) * 4;
    float4 a_reg[2];

    // B staging via cp.async: 128 rows x 8 16B-groups = 1024 slots, <=3/thread
    uint32_t bsa[3];
    const uint32_t* wsrc[3];
    bool bval[3];
#pragma unroll
    for (int i = 0; i < 3; i++) {
        int idx = tid + i * 384;
        bval[i] = (idx < 1024);
        int n   = bval[i] ? (idx >> 3) : 0;
        int acg = bval[i] ? ((idx & 7) * 4) : 0;
        bsa[i]  = smem_u32p(&Bs[n * 36 + acg]);
        wsrc[i] = g_Wp_tf + (long)(col0 + n) * 512 + acg;
    }
    const uint32_t bufB_bytes = 4608 * 4;

    float acc[2][4][4];
#pragma unroll
    for (int mf = 0; mf < 2; mf++)
#pragma unroll
        for (int nf = 0; nf < 4; nf++)
#pragma unroll
            for (int v = 0; v < 4; v++) acc[mf][nf][v] = 0.f;

    // prologue: B chunk0 via cp.async; A chunk0 via regs + cvt
#pragma unroll
    for (int i = 0; i < 3; i++) if (bval[i]) cp16(bsa[i], wsrc[i]);
    CP_COMMIT();
#pragma unroll
    for (int i = 0; i < 2; i++)
        a_reg[i] = *(const float4*)(x + (row0 + ar[i]) * NFEAT_ + ac);
#pragma unroll
    for (int i = 0; i < 2; i++) {
        uint32_t* d = As + ar[i] * 36 + ac;
        *(uint4*)d = make_uint4(f2tf(a_reg[i].x), f2tf(a_reg[i].y),
                                f2tf(a_reg[i].z), f2tf(a_reg[i].w));
    }
    CP_WAIT0();
    __syncthreads();

    for (int it = 0; it < 16; it++) {
        const int buf = it & 1;
        if (it < 15) {
            const int ks = (it + 1) * 32;
#pragma unroll
            for (int i = 0; i < 3; i++)
                if (bval[i]) cp16(bsa[i] + (buf ^ 1) * bufB_bytes, wsrc[i] + ks);
            CP_COMMIT();
#pragma unroll
            for (int i = 0; i < 2; i++)
                a_reg[i] = *(const float4*)(x + (row0 + ar[i]) * NFEAT_ + ks + ac);
        }
        const uint32_t* Ab = As + buf * 3456;
        const uint32_t* Bb = Bs + buf * 4608;
        // per-warp rotated kk order
#pragma unroll
        for (int ki = 0; ki < 4; ki++) {
            const int kk = (ki + warp) & 3;
            const int k8 = kk * 8;
            uint32_t af[2][4], bf[4][2];
#pragma unroll
            for (int mf = 0; mf < 2; mf++) {
                const int rb = warpM * 32 + mf * 16;
                af[mf][0] = Ab[(rb + g)     * 36 + k8 + t];
                af[mf][1] = Ab[(rb + g + 8) * 36 + k8 + t];
                af[mf][2] = Ab[(rb + g)     * 36 + k8 + t + 4];
                af[mf][3] = Ab[(rb + g + 8) * 36 + k8 + t + 4];
            }
#pragma unroll
            for (int nf = 0; nf < 4; nf++) {
                const int nb = warpN * 32 + nf * 8;
                bf[nf][0] = Bb[(nb + g) * 36 + k8 + t];
                bf[nf][1] = Bb[(nb + g) * 36 + k8 + t + 4];
            }
#pragma unroll
            for (int mf = 0; mf < 2; mf++)
#pragma unroll
                for (int nf = 0; nf < 4; nf++)
                    mma8(acc[mf][nf], af[mf], bf[nf]);
        }
        if (it < 15) {
            uint32_t* An = As + (buf ^ 1) * 3456;
#pragma unroll
            for (int i = 0; i < 2; i++) {
                uint32_t* d = An + ar[i] * 36 + ac;
                *(uint4*)d = make_uint4(f2tf(a_reg[i].x), f2tf(a_reg[i].y),
                                        f2tf(a_reg[i].z), f2tf(a_reg[i].w));
            }
            CP_WAIT0();
        }
        __syncthreads();
    }

    // epilogue: two 64-col halves through smem (Cs [96][68] reuses As region)
    float* Cs = (float*)As;
#pragma unroll
    for (int half = 0; half < 2; half++) {
        if ((warpN >> 1) == half) {
#pragma unroll
            for (int mf = 0; mf < 2; mf++)
#pragma unroll
                for (int nf = 0; nf < 4; nf++) {
                    const int r  = warpM * 32 + mf * 16 + g;
                    const int cc = (warpN & 1) * 32 + nf * 8 + t * 2;
                    Cs[r * 68 + cc]           = acc[mf][nf][0];
                    Cs[r * 68 + cc + 1]       = acc[mf][nf][1];
                    Cs[(r + 8) * 68 + cc]     = acc[mf][nf][2];
                    Cs[(r + 8) * 68 + cc + 1] = acc[mf][nf][3];
                }
        }
        __syncthreads();
        if (tid < 256) {
            const int ty = tid >> 4, tx = tid & 15;
            const int node = node0 + ty;
            const int cg = half * 64 + tx * 4;
            float4 b4 = *(const float4*)(bp + col0 + cg);
            float bv[4] = {b4.x, b4.y, b4.z, b4.w};
            float zr[4];
#pragma unroll
            for (int c = 0; c < 4; c++) {
                float h[NHOPS], am[NHOPS], s[NHOPS];
#pragma unroll
                for (int r = 0; r < NHOPS; r++) {
                    float v = Cs[(ty * 6 + r) * 68 + tx * 4 + c] + bv[c];
                    v = v > 0.f ? v : NEG_ * v;
                    h[r]  = v;
                    am[r] = v * atts[half * 384 + r * 64 + tx * 4 + c];
                }
                float m = -1e30f;
#pragma unroll
                for (int r = 0; r < NHOPS; r++) {
                    float u = am[0] + am[r];
                    u = u > 0.f ? u : NEG_ * u;
                    s[r] = u;
                    m = fmaxf(m, u);
                }
                float den = 0.f, num = 0.f;
#pragma unroll
                for (int r = 0; r < NHOPS; r++) {
                    float w = expf(s[r] - m);
                    den += w;
                    num += h[r] * w;
                }
                zr[c] = num / den;
            }
            *(float4*)&g_z1[(long)node * 512 + col0 + cg] =
                make_float4(zr[0], zr[1], zr[2], zr[3]);
        }
        __syncthreads();
    }
}

// ---------------------------------------------------------------------------
// K2 (tf32 mma, per-warp kk rotation): z = lrelu(z1 @ W_post^T + b),
// plus per-row sum-of-squares + norm. Block 128x256, 512 threads,
// warp tile 32x64. Dynamic smem: As[2][128][36] | Bs[2][256][36] = 110592 B.
// ---------------------------------------------------------------------------
__global__ void __launch_bounds__(512) smn_k2_tc(
    const float* __restrict__ bq, float* __restrict__ dout)
{
    extern __shared__ uint32_t dynsmem[];
    uint32_t* As = dynsmem;                   // 2 * 128*36
    uint32_t* Bs = As + 2 * 128 * 36;         // 2 * 256*36
    __shared__ float bias_s[256];

    const int tid  = threadIdx.x;
    const int lane = tid & 31, warp = tid >> 5;
    const int warpM = warp >> 2, warpN = warp & 3;
    const int g = lane >> 2, t = lane & 3;
    const long row0 = (long)blockIdx.x * 128;

    if (tid < 256) bias_s[tid] = bq[tid];

    const int ar[2] = { (tid + 0) >> 3, (tid + 512) >> 3 };
    const int bn[4] = { (tid + 0) >> 3,    (tid + 512) >> 3,
                        (tid + 1024) >> 3, (tid + 1536) >> 3 };
    const int ac    = (tid & 7) * 4;
    float4 a_reg[2];

    uint32_t bsa[4];
#pragma unroll
    for (int i = 0; i < 4; i++)
        bsa[i] = smem_u32p(&Bs[bn[i] * 36 + ac]);
    const uint32_t bufB_bytes = 9216 * 4;
    const uint32_t* wsrc[4];
#pragma unroll
    for (int i = 0; i < 4; i++)
        wsrc[i] = g_Wq_tf + (long)bn[i] * 512 + ac;

    float acc[2][8][4];
#pragma unroll
    for (int mf = 0; mf < 2; mf++)
#pragma unroll
        for (int nf = 0; nf < 8; nf++)
#pragma unroll
            for (int v = 0; v < 4; v++) acc[mf][nf][v] = 0.f;

#pragma unroll
    for (int i = 0; i < 4; i++) cp16(bsa[i], wsrc[i]);
    CP_COMMIT();
#pragma unroll
    for (int i = 0; i < 2; i++)
        a_reg[i] = *(const float4*)(g_z1 + (row0 + ar[i]) * 512 + ac);
#pragma unroll
    for (int i = 0; i < 2; i++) {
        uint32_t* d = As + ar[i] * 36 + ac;
        *(uint4*)d = make_uint4(f2tf(a_reg[i].x), f2tf(a_reg[i].y),
                                f2tf(a_reg[i].z), f2tf(a_reg[i].w));
    }
    CP_WAIT0();
    __syncthreads();

    for (int it = 0; it < 16; it++) {
        const int buf = it & 1;
        if (it < 15) {
            const int ks = (it + 1) * 32;
#pragma unroll
            for (int i = 0; i < 4; i++)
                cp16(bsa[i] + (buf ^ 1) * bufB_bytes, wsrc[i] + ks);
            CP_COMMIT();
#pragma unroll
            for (int i = 0; i < 2; i++)
                a_reg[i] = *(const float4*)(g_z1 + (row0 + ar[i]) * 512 + ks + ac);
        }
        const uint32_t* Ab = As + buf * 4608;
        const uint32_t* Bb = Bs + buf * 9216;
#pragma unroll
        for (int ki = 0; ki < 4; ki++) {
            const int kk = (ki + warp) & 3;
            const int k8 = kk * 8;
            uint32_t af[2][4], bf[8][2];
#pragma unroll
            for (int mf = 0; mf < 2; mf++) {
                const int rb = warpM * 32 + mf * 16;
                af[mf][0] = Ab[(rb + g)     * 36 + k8 + t];
                af[mf][1] = Ab[(rb + g + 8) * 36 + k8 + t];
                af[mf][2] = Ab[(rb + g)     * 36 + k8 + t + 4];
                af[mf][3] = Ab[(rb + g + 8) * 36 + k8 + t + 4];
            }
#pragma unroll
            for (int nf = 0; nf < 8; nf++) {
                const int nb = warpN * 64 + nf * 8;
                bf[nf][0] = Bb[(nb + g) * 36 + k8 + t];
                bf[nf][1] = Bb[(nb + g) * 36 + k8 + t + 4];
            }
#pragma unroll
            for (int mf = 0; mf < 2; mf++)
#pragma unroll
                for (int nf = 0; nf < 8; nf++)
                    mma8(acc[mf][nf], af[mf], bf[nf]);
        }
        if (it < 15) {
            uint32_t* An = As + (buf ^ 1) * 4608;
#pragma unroll
            for (int i = 0; i < 2; i++) {
                uint32_t* d = An + ar[i] * 36 + ac;
                *(uint4*)d = make_uint4(f2tf(a_reg[i].x), f2tf(a_reg[i].y),
                                        f2tf(a_reg[i].z), f2tf(a_reg[i].w));
            }
            CP_WAIT0();
        }
        __syncthreads();
    }

    // epilogue: bias + lrelu + store z + per-row sum of squares
    float* part = (float*)As;     // [128][4]
    float zp[4] = {0.f, 0.f, 0.f, 0.f};
#pragma unroll
    for (int mf = 0; mf < 2; mf++) {
#pragma unroll
        for (int nf = 0; nf < 8; nf++) {
            const int rl  = warpM * 32 + mf * 16 + g;
            const int col = warpN * 64 + nf * 8 + t * 2;
            float v0 = acc[mf][nf][0] + bias_s[col];
            float v1 = acc[mf][nf][1] + bias_s[col + 1];
            float v2 = acc[mf][nf][2] + bias_s[col];
            float v3 = acc[mf][nf][3] + bias_s[col + 1];
            v0 = v0 > 0.f ? v0 : NEG_ * v0;
            v1 = v1 > 0.f ? v1 : NEG_ * v1;
            v2 = v2 > 0.f ? v2 : NEG_ * v2;
            v3 = v3 > 0.f ? v3 : NEG_ * v3;
            *(float2*)&dout[Z_OFF + (row0 + rl) * 256 + col] =
                make_float2(v0, v1);
            *(float2*)&dout[Z_OFF + (row0 + rl + 8) * 256 + col] =
                make_float2(v2, v3);
            zp[mf * 2]     += v0 * v0 + v1 * v1;
            zp[mf * 2 + 1] += v2 * v2 + v3 * v3;
        }
    }
#pragma unroll
    for (int j = 0; j < 4; j++) {
        zp[j] += __shfl_xor_sync(0xffffffffu, zp[j], 1);
        zp[j] += __shfl_xor_sync(0xffffffffu, zp[j], 2);
    }
    __syncthreads();
    if (t == 0) {
#pragma unroll
        for (int j = 0; j < 4; j++) {
            const int rl = warpM * 32 + (j >> 1) * 16 + g + (j & 1) * 8;
            part[rl * 4 + warpN] = zp[j];
        }
    }
    __syncthreads();
    if (tid < 128) {
        float s = part[tid * 4] + part[tid * 4 + 1]
                + part[tid * 4 + 2] + part[tid * 4 + 3];
        g_zsq[row0 + tid] = s;
        g_zn[row0 + tid]  = fmaxf(sqrtf(s), COS_EPS_);
    }
}

// ---------------------------------------------------------------------------
// K3 (tf32 mma, measured 24.4us): out = z @ ssfn; dist/sim; log-softmaxes.
// dynsmem u32: Bs 10240 | As 2*4096  (=73728 B)
// ---------------------------------------------------------------------------
__global__ void __launch_bounds__(256) smn_k3_tc(float* __restrict__ dout)
{
    extern __shared__ uint32_t dynsmem[];
    uint32_t* Bs = dynsmem;            // 5 n8grp * 32 kk * 64
    uint32_t* As = dynsmem + 10240;    // 2 * 8 tiles * 4 kk * 128
    __shared__ float csq_s[NCLASS_], cn_s[NCLASS_];

    const int tid  = threadIdx.x;
    const int lane = tid & 31, warp = tid >> 5;
    const int g = lane >> 2, t = lane & 3;
    const long row0 = (long)blockIdx.x * 128;
    const float* zg = dout + Z_OFF;

    for (int e = tid; e < NSSF_ * NCLASS_; e += 256) {
        int k = e / NCLASS_, n = e - k * NCLASS_;
        float v = dout[SSFN_OFF + e];
        int kk = k >> 3, kp = k & 7, tt = kp & 3, hi2 = kp >> 2;
        int phys = (((n & 7) * 4 + tt) + kk * 2) & 31;
        Bs[((n >> 3) * 32 + kk) * 64 + phys * 2 + hi2] = f2tf(v);
    }
    if (tid < NCLASS_) { csq_s[tid] = g_csq[tid]; cn_s[tid] = g_cn[tid]; }

    const int ar[4] = { (tid) >> 3, (tid + 256) >> 3,
                        (tid + 512) >> 3, (tid + 768) >> 3 };
    const int ac  = (tid & 7) * 4;
    const int kkt = ac >> 3, hit = (ac >> 2) & 1, rot = kkt * 2;
    float4 a_reg[4];

    auto stageA3 = [&](uint32_t* dstbuf) {
#pragma unroll
        for (int i = 0; i < 4; i++) {
            const int r = ar[i];
            uint32_t* d = dstbuf + (((r >> 4) * 4 + kkt) * 128)
                        + ((r >> 3) & 1) + 2 * hit;
            const int l0 = (r & 7) * 4;
            d[(((l0 + 0) + rot) & 31) * 4] = f2tf(a_reg[i].x);
            d[(((l0 + 1) + rot) & 31) * 4] = f2tf(a_reg[i].y);
            d[(((l0 + 2) + rot) & 31) * 4] = f2tf(a_reg[i].z);
            d[(((l0 + 3) + rot) & 31) * 4] = f2tf(a_reg[i].w);
        }
    };

    float acc[5][4];
#pragma unroll
    for (int nf = 0; nf < 5; nf++)
#pragma unroll
        for (int v = 0; v < 4; v++) acc[nf][v] = 0.f;

#pragma unroll
    for (int i = 0; i < 4; i++)
        a_reg[i] = *(const float4*)(zg + (row0 + ar[i]) * 256 + ac);
    stageA3(As);
    __syncthreads();

    for (int it = 0; it < 8; it++) {
        const int buf = it & 1;
        if (it < 7) {
            const int ks = (it + 1) * 32;
#pragma unroll
            for (int i = 0; i < 4; i++)
                a_reg[i] = *(const float4*)(zg + (row0 + ar[i]) * 256 + ks + ac);
        }
        const uint32_t* Ab = As + buf * 4096;
#pragma unroll
        for (int kk = 0; kk < 4; kk++) {
            const int kkg = it * 4 + kk;
            const int prA = (lane + kk * 2) & 31;
            const int prB = (lane + kkg * 2) & 31;
            uint4 av = *(const uint4*)&Ab[(warp * 4 + kk) * 128 + prA * 4];
#pragma unroll
            for (int nf = 0; nf < 5; nf++) {
                uint2 bv = *(const uint2*)&Bs[(nf * 32 + kkg) * 64 + prB * 2];
                mma8(acc[nf], reinterpret_cast<const uint32_t*>(&av),
                     reinterpret_cast<const uint32_t*>(&bv));
            }
        }
        if (it < 7) stageA3(As + (buf ^ 1) * 4096);
        __syncthreads();
    }

#pragma unroll
    for (int rs = 0; rs < 2; rs++) {
        const long row = row0 + warp * 16 + g + rs * 8;
        const float zsq = g_zsq[row];
        const float zn  = g_zn[row];
        float dv[5][2], sv[5][2], av[5][2];
        float md = -1e30f, ms = -1e30f;
#pragma unroll
        for (int nf = 0; nf < 5; nf++) {
#pragma unroll
            for (int u = 0; u < 2; u++) {
                const int col = nf * 8 + t * 2 + u;
                float a = acc[nf][rs * 2 + u];
                av[nf][u] = a;
                float d = -sqrtf(fmaxf(zsq + csq_s[col] - 2.f * a, 0.f));
                float s = a / (zn * cn_s[col]);
                dv[nf][u] = d; sv[nf][u] = s;
                md = fmaxf(md, d); ms = fmaxf(ms, s);
            }
        }
        md = fmaxf(md, __shfl_xor_sync(0xffffffffu, md, 1));
        md = fmaxf(md, __shfl_xor_sync(0xffffffffu, md, 2));
        ms = fmaxf(ms, __shfl_xor_sync(0xffffffffu, ms, 1));
        ms = fmaxf(ms, __shfl_xor_sync(0xffffffffu, ms, 2));
        float ed = 0.f, es = 0.f;
#pragma unroll
        for (int nf = 0; nf < 5; nf++)
#pragma unroll
            for (int u = 0; u < 2; u++) {
                ed += expf(dv[nf][u] - md);
                es += expf(sv[nf][u] - ms);
            }
        ed += __shfl_xor_sync(0xffffffffu, ed, 1);
        ed += __shfl_xor_sync(0xffffffffu, ed, 2);
        es += __shfl_xor_sync(0xffffffffu, es, 1);
        es += __shfl_xor_sync(0xffffffffu, es, 2);
        const float lse_d = md + logf(ed);
        const float lse_s = ms + logf(es);
#pragma unroll
        for (int nf = 0; nf < 5; nf++) {
            const int col = nf * 8 + t * 2;
            *(float2*)&dout[OUT_OFF + row * NCLASS_ + col] =
                make_float2(av[nf][0], av[nf][1]);
            *(float2*)&dout[LOSS_OFF + row * NCLASS_ + col] = make_float2(
                0.5f * ((dv[nf][0] - lse_d) + (sv[nf][0] - lse_s)),
                0.5f * ((dv[nf][1] - lse_d) + (sv[nf][1] - lse_s)));
        }
    }
}

// ---------------------------------------------------------------------------
extern "C" void kernel_launch(void* const* d_in, const int* in_sizes, int n_in,
                              void* d_out, int out_size)
{
    const float* x      = (const float*)d_in[0];
    const float* W_pre  = (const float*)d_in[1];
    const float* b_pre  = (const float*)d_in[2];
    const float* att    = (const float*)d_in[3];
    const float* W_post = (const float*)d_in[4];
    const float* b_post = (const float*)d_in[5];
    const float* ssf    = (const float*)d_in[6];
    const float* sigma  = (const float*)d_in[7];
    float* dout = (float*)d_out;

    const int K1_SMEM = (768 + 2 * 96 * 36 + 2 * 128 * 36) * 4;   // 67584
    const int K2_SMEM = (2 * 128 * 36 + 2 * 256 * 36) * 4;        // 110592
    const int K3_SMEM = (10240 + 2 * 4096) * 4;                   // 73728
    cudaFuncSetAttribute(smn_k1_tc,
                         cudaFuncAttributeMaxDynamicSharedMemorySize, K1_SMEM);
    cudaFuncSetAttribute(smn_k2_tc,
                         cudaFuncAttributeMaxDynamicSharedMemorySize, K2_SMEM);
    cudaFuncSetAttribute(smn_k3_tc,
                         cudaFuncAttributeMaxDynamicSharedMemorySize, K3_SMEM);

    smn_wcvt_ssf<<<1537, 256>>>(W_pre, W_post, ssf, sigma, dout);
    smn_k1_tc<<<dim3(4, NN / 16), 384, K1_SMEM>>>(x, b_pre, att);
    smn_k2_tc<<<NN / 128, 512, K2_SMEM>>>(b_post, dout);
    smn_k3_tc<<<NN / 128, 256, K3_SMEM>>>(dout);
}

// round 11
// speedup vs baseline: 1.5066x; 1.5066x over previous
#include <cuda_runtime.h>
#include <cuda_fp16.h>
#include <math.h>
#include <stdint.h>

#define NN      32768
#define NHOPS   6
#define NFEAT_  512
#define NSSF_   256
#define NCLASS_ 40
#define NEG_    0.2f
#define COS_EPS_ 1e-6f

// output layout (flattened tuple, element offsets)
#define OUT_OFF   0
#define SSFN_OFF  (NN*NCLASS_)                    // 1310720
#define Z_OFF     (SSFN_OFF + NSSF_*NCLASS_)      // 1320960
#define LOSS_OFF  (Z_OFF + NN*NSSF_)              // 9709568
#define SIGMA_OFF (LOSS_OFF + NN*NCLASS_)         // 11020288

// scratch (static device globals — no runtime allocation)
__device__ float g_z1[(long)NN * 512];
__device__ float g_zsq[NN];
__device__ float g_zn[NN];
__device__ float g_csq[NCLASS_];
__device__ float g_cn[NCLASS_];
__device__ __half g_Wp_h[512 * 512];   // W_pre pre-converted to fp16
__device__ __half g_Wq_h[256 * 512];   // W_post pre-converted to fp16

// ---------------------------------------------------------------------------
// helpers
// ---------------------------------------------------------------------------
__device__ __forceinline__ uint32_t f2tf(float x) {
    uint32_t y;
    asm("cvt.rna.tf32.f32 %0, %1;" : "=r"(y) : "f"(x));
    return y;
}
__device__ __forceinline__ uint32_t f2h2(float a, float b) {
    __half2 h = __floats2half2_rn(a, b);
    return *reinterpret_cast<uint32_t*>(&h);
}
// tf32 m16n8k8 (K3 only)
__device__ __forceinline__ void mma8(float c[4], const uint32_t a[4],
                                     const uint32_t b[2]) {
    asm volatile(
        "mma.sync.aligned.m16n8k8.row.col.f32.tf32.tf32.f32 "
        "{%0,%1,%2,%3}, {%4,%5,%6,%7}, {%8,%9}, {%0,%1,%2,%3};\n"
        : "+f"(c[0]), "+f"(c[1]), "+f"(c[2]), "+f"(c[3])
        : "r"(a[0]), "r"(a[1]), "r"(a[2]), "r"(a[3]), "r"(b[0]), "r"(b[1]));
}
// fp16 m16n8k16 (K1/K2)
__device__ __forceinline__ void mma16(float c[4], const uint32_t a[4],
                                      const uint32_t b[2]) {
    asm volatile(
        "mma.sync.aligned.m16n8k16.row.col.f32.f16.f16.f32 "
        "{%0,%1,%2,%3}, {%4,%5,%6,%7}, {%8,%9}, {%0,%1,%2,%3};\n"
        : "+f"(c[0]), "+f"(c[1]), "+f"(c[2]), "+f"(c[3])
        : "r"(a[0]), "r"(a[1]), "r"(a[2]), "r"(a[3]), "r"(b[0]), "r"(b[1]));
}
__device__ __forceinline__ uint32_t smem_u32p(const void* p) {
    uint32_t a;
    asm("{ .reg .u64 t; cvta.to.shared.u64 t, %1; cvt.u32.u64 %0, t; }"
        : "=r"(a) : "l"(p));
    return a;
}
__device__ __forceinline__ void cp16(uint32_t saddr, const void* g) {
    asm volatile("cp.async.ca.shared.global [%0], [%1], 16;"
                 :: "r"(saddr), "l"(g));
}
#define CP_COMMIT() asm volatile("cp.async.commit_group;")
#define CP_WAIT0()  asm volatile("cp.async.wait_group 0;")

// ---------------------------------------------------------------------------
// Kw: weight fp16 pre-convert (blocks 0..1535) + K0 ssf work (block 1536).
// ---------------------------------------------------------------------------
__global__ void __launch_bounds__(256) smn_wcvt_ssf(
    const float* __restrict__ Wp, const float* __restrict__ Wq,
    const float* __restrict__ ssf, const float* __restrict__ sigma,
    float* __restrict__ dout)
{
    __shared__ float fbuf[NSSF_ * NCLASS_];
    __shared__ int   cnt_s[256];
    const int tid = threadIdx.x;

    if (blockIdx.x < 1536) {
        int i = blockIdx.x * 256 + tid;
        if (i < 512 * 512) {
            g_Wp_h[i] = __float2half_rn(Wp[i]);
        } else {
            int j = i - 512 * 512;
            if (j < 256 * 512) g_Wq_h[j] = __float2half_rn(Wq[j]);
        }
        return;
    }

    // ---- K0: exact threshold select + ssf_norm + column norms + sigma ----
    unsigned* keys = reinterpret_cast<unsigned*>(fbuf);
    for (int i = tid; i < NSSF_ * NCLASS_; i += 256)
        keys[i] = __float_as_uint(fabsf(ssf[i]));
    __syncthreads();

    unsigned lo = 0u, hi = 0x7f800000u;
    while (lo < hi) {
        unsigned mid = (lo + hi) >> 1;
        int c = 0;
        for (int i = tid; i < NSSF_ * NCLASS_; i += 256) c += (keys[i] <= mid);
        cnt_s[tid] = c;
        __syncthreads();
        for (int s = 128; s > 0; s >>= 1) {
            if (tid < s) cnt_s[tid] += cnt_s[tid + s];
            __syncthreads();
        }
        int total = cnt_s[0];
        __syncthreads();
        if (total >= 5121) hi = mid; else lo = mid + 1;
    }
    const float thr = __uint_as_float(lo);

    float row[NCLASS_];
    float rs = 0.f;
    const float* srow = ssf + tid * NCLASS_;
#pragma unroll
    for (int j = 0; j < NCLASS_; j++) {
        float v = srow[j];
        v = (fabsf(v) >= thr) ? v : 0.f;
        row[j] = v;
        rs += fabsf(v);
    }
    const float inv = 1.f / fmaxf(rs, 1e-12f);
#pragma unroll
    for (int j = 0; j < NCLASS_; j++) {
        float v = row[j] * inv;
        dout[SSFN_OFF + tid * NCLASS_ + j] = v;
        fbuf[tid * NCLASS_ + j] = v;
    }
    __syncthreads();

    if (tid < NCLASS_) {
        float c2 = 0.f;
        for (int i = 0; i < NSSF_; i++) {
            float v = fbuf[i * NCLASS_ + tid];
            c2 += v * v;
        }
        g_csq[tid] = c2;
        g_cn[tid]  = fmaxf(sqrtf(c2), COS_EPS_);
    }
    if (tid < 2) dout[SIGMA_OFF + tid] = sigma[tid];
}

// ---------------------------------------------------------------------------
// K1 (fp16 m16n8k16, round-9 tiling, 2 blocks/SM): h = lrelu(x @ W_pre^T + b)
// -> hop softmax. Block 96x128, 8 warps, warp tile 48x32.
// smem in half2-units (u32): atts 768f | As[2][96][20] | Bs[2][128][20]
// = (768 + 3840 + 5120) * 4 = 38912 B.
// ---------------------------------------------------------------------------
__global__ void __launch_bounds__(256, 2) smn_k1_tc(
    const float* __restrict__ x,
    const float* __restrict__ bp, const float* __restrict__ att)
{
    extern __shared__ uint32_t dynsmem[];
    float*    atts = (float*)dynsmem;         // 768
    uint32_t* As   = dynsmem + 768;           // 2 * 96*20
    uint32_t* Bs   = As + 2 * 96 * 20;        // 2 * 128*20

    const int tid  = threadIdx.x;
    const int lane = tid & 31, warp = tid >> 5;
    const int warpM = warp >> 2, warpN = warp & 3;
    const int g = lane >> 2, t = lane & 3;
    const int node0 = blockIdx.y * 16;
    const int col0  = blockIdx.x * 128;
    const long row0 = (long)node0 * NHOPS;

    for (int i = tid; i < 768; i += 256)
        atts[i] = att[2 * blockIdx.x * 384 + i];

    // A staging: 96 rows x 8 float4 groups, 3 per thread (fp32 -> half2 pairs)
    const int ar[3] = { (tid + 0)   >> 3, (tid + 256) >> 3, (tid + 512) >> 3 };
    const int ac    = (tid & 7) * 4;          // k-offset (in halves/floats)
    const int au    = ac >> 1;                // unit column in As
    float4 a_reg[3];

    // B staging via cp.async: 128 rows x 4 16B-slots = 512, 2 per thread
    uint32_t bsa[2];
    const __half* wsrc[2];
#pragma unroll
    for (int i = 0; i < 2; i++) {
        int idx = tid + i * 256;
        int n   = idx >> 2;
        int kh  = (idx & 3) * 8;               // k-offset in halves
        bsa[i]  = smem_u32p(&Bs[n * 20 + (kh >> 1)]);
        wsrc[i] = g_Wp_h + (long)(col0 + n) * 512 + kh;
    }
    const uint32_t bufB_bytes = 2560 * 4;

    float acc[3][4][4];
#pragma unroll
    for (int mf = 0; mf < 3; mf++)
#pragma unroll
        for (int nf = 0; nf < 4; nf++)
#pragma unroll
            for (int v = 0; v < 4; v++) acc[mf][nf][v] = 0.f;

    // prologue
#pragma unroll
    for (int i = 0; i < 2; i++) cp16(bsa[i], wsrc[i]);
    CP_COMMIT();
#pragma unroll
    for (int i = 0; i < 3; i++)
        a_reg[i] = *(const float4*)(x + (row0 + ar[i]) * NFEAT_ + ac);
#pragma unroll
    for (int i = 0; i < 3; i++) {
        uint32_t* d = As + ar[i] * 20 + au;
        *(uint2*)d = make_uint2(f2h2(a_reg[i].x, a_reg[i].y),
                                f2h2(a_reg[i].z, a_reg[i].w));
    }
    CP_WAIT0();
    __syncthreads();

    for (int it = 0; it < 16; it++) {
        const int buf = it & 1;
        if (it < 15) {
            const int ks = (it + 1) * 32;
#pragma unroll
            for (int i = 0; i < 2; i++)
                cp16(bsa[i] + (buf ^ 1) * bufB_bytes, wsrc[i] + ks);
            CP_COMMIT();
#pragma unroll
            for (int i = 0; i < 3; i++)
                a_reg[i] = *(const float4*)(x + (row0 + ar[i]) * NFEAT_ + ks + ac);
        }
        const uint32_t* Ab = As + buf * 1920;
        const uint32_t* Bb = Bs + buf * 2560;
        // 2 k16 groups per 32-k chunk, per-warp rotated
#pragma unroll
        for (int gi = 0; gi < 2; gi++) {
            const int grp = (gi + warp) & 1;
            const int k8u = grp * 8;           // unit offset of this k16 group
            uint32_t af[3][4], bf[4][2];
#pragma unroll
            for (int mf = 0; mf < 3; mf++) {
                const int rb = warpM * 48 + mf * 16;
                af[mf][0] = Ab[(rb + g)     * 20 + k8u + t];
                af[mf][1] = Ab[(rb + g + 8) * 20 + k8u + t];
                af[mf][2] = Ab[(rb + g)     * 20 + k8u + t + 4];
                af[mf][3] = Ab[(rb + g + 8) * 20 + k8u + t + 4];
            }
#pragma unroll
            for (int nf = 0; nf < 4; nf++) {
                const int nb = warpN * 32 + nf * 8;
                bf[nf][0] = Bb[(nb + g) * 20 + k8u + t];
                bf[nf][1] = Bb[(nb + g) * 20 + k8u + t + 4];
            }
#pragma unroll
            for (int mf = 0; mf < 3; mf++)
#pragma unroll
                for (int nf = 0; nf < 4; nf++)
                    mma16(acc[mf][nf], af[mf], bf[nf]);
        }
        if (it < 15) {
            uint32_t* An = As + (buf ^ 1) * 1920;
#pragma unroll
            for (int i = 0; i < 3; i++) {
                uint32_t* d = An + ar[i] * 20 + au;
                *(uint2*)d = make_uint2(f2h2(a_reg[i].x, a_reg[i].y),
                                        f2h2(a_reg[i].z, a_reg[i].w));
            }
            CP_WAIT0();
        }
        __syncthreads();
    }

    // epilogue: two 64-col halves through smem (Cs [96][68] reuses As region)
    float* Cs = (float*)As;
#pragma unroll
    for (int half = 0; half < 2; half++) {
        if ((warpN >> 1) == half) {
#pragma unroll
            for (int mf = 0; mf < 3; mf++)
#pragma unroll
                for (int nf = 0; nf < 4; nf++) {
                    const int r  = warpM * 48 + mf * 16 + g;
                    const int cc = (warpN & 1) * 32 + nf * 8 + t * 2;
                    Cs[r * 68 + cc]           = acc[mf][nf][0];
                    Cs[r * 68 + cc + 1]       = acc[mf][nf][1];
                    Cs[(r + 8) * 68 + cc]     = acc[mf][nf][2];
                    Cs[(r + 8) * 68 + cc + 1] = acc[mf][nf][3];
                }
        }
        __syncthreads();
        {
            const int ty = tid >> 4, tx = tid & 15;
            const int node = node0 + ty;
            const int cg = half * 64 + tx * 4;
            float4 b4 = *(const float4*)(bp + col0 + cg);
            float bv[4] = {b4.x, b4.y, b4.z, b4.w};
            float zr[4];
#pragma unroll
            for (int c = 0; c < 4; c++) {
                float h[NHOPS], am[NHOPS], s[NHOPS];
#pragma unroll
                for (int r = 0; r < NHOPS; r++) {
                    float v = Cs[(ty * 6 + r) * 68 + tx * 4 + c] + bv[c];
                    v = v > 0.f ? v : NEG_ * v;
                    h[r]  = v;
                    am[r] = v * atts[half * 384 + r * 64 + tx * 4 + c];
                }
                float m = -1e30f;
#pragma unroll
                for (int r = 0; r < NHOPS; r++) {
                    float u = am[0] + am[r];
                    u = u > 0.f ? u : NEG_ * u;
                    s[r] = u;
                    m = fmaxf(m, u);
                }
                float den = 0.f, num = 0.f;
#pragma unroll
                for (int r = 0; r < NHOPS; r++) {
                    float w = expf(s[r] - m);
                    den += w;
                    num += h[r] * w;
                }
                zr[c] = num / den;
            }
            *(float4*)&g_z1[(long)node * 512 + col0 + cg] =
                make_float4(zr[0], zr[1], zr[2], zr[3]);
        }
        __syncthreads();
    }
}

// ---------------------------------------------------------------------------
// K2 (fp16 m16n8k16): z = lrelu(z1 @ W_post^T + b) + zsq/zn.
// Block 128x256, 512 threads, warp tile 32x64.
// smem units: As[2][128][20] | Bs[2][256][20] = (5120 + 10240) * 4 = 61440 B.
// ---------------------------------------------------------------------------
__global__ void __launch_bounds__(512) smn_k2_tc(
    const float* __restrict__ bq, float* __restrict__ dout)
{
    extern __shared__ uint32_t dynsmem[];
    uint32_t* As = dynsmem;                   // 2 * 128*20
    uint32_t* Bs = As + 2 * 128 * 20;         // 2 * 256*20
    __shared__ float bias_s[256];

    const int tid  = threadIdx.x;
    const int lane = tid & 31, warp = tid >> 5;
    const int warpM = warp >> 2, warpN = warp & 3;
    const int g = lane >> 2, t = lane & 3;
    const long row0 = (long)blockIdx.x * 128;

    if (tid < 256) bias_s[tid] = bq[tid];

    const int ar[2] = { (tid + 0) >> 3, (tid + 512) >> 3 };
    const int ac    = (tid & 7) * 4;
    const int au    = ac >> 1;
    float4 a_reg[2];

    // B: 256 rows x 4 16B-slots = 1024, 2 per thread
    uint32_t bsa[2];
    const __half* wsrc[2];
#pragma unroll
    for (int i = 0; i < 2; i++) {
        int idx = tid + i * 512;
        int n   = idx >> 2;
        int kh  = (idx & 3) * 8;
        bsa[i]  = smem_u32p(&Bs[n * 20 + (kh >> 1)]);
        wsrc[i] = g_Wq_h + (long)n * 512 + kh;
    }
    const uint32_t bufB_bytes = 5120 * 4;

    float acc[2][8][4];
#pragma unroll
    for (int mf = 0; mf < 2; mf++)
#pragma unroll
        for (int nf = 0; nf < 8; nf++)
#pragma unroll
            for (int v = 0; v < 4; v++) acc[mf][nf][v] = 0.f;

#pragma unroll
    for (int i = 0; i < 2; i++) cp16(bsa[i], wsrc[i]);
    CP_COMMIT();
#pragma unroll
    for (int i = 0; i < 2; i++)
        a_reg[i] = *(const float4*)(g_z1 + (row0 + ar[i]) * 512 + ac);
#pragma unroll
    for (int i = 0; i < 2; i++) {
        uint32_t* d = As + ar[i] * 20 + au;
        *(uint2*)d = make_uint2(f2h2(a_reg[i].x, a_reg[i].y),
                                f2h2(a_reg[i].z, a_reg[i].w));
    }
    CP_WAIT0();
    __syncthreads();

    for (int it = 0; it < 16; it++) {
        const int buf = it & 1;
        if (it < 15) {
            const int ks = (it + 1) * 32;
#pragma unroll
            for (int i = 0; i < 2; i++)
                cp16(bsa[i] + (buf ^ 1) * bufB_bytes, wsrc[i] + ks);
            CP_COMMIT();
#pragma unroll
            for (int i = 0; i < 2; i++)
                a_reg[i] = *(const float4*)(g_z1 + (row0 + ar[i]) * 512 + ks + ac);
        }
        const uint32_t* Ab = As + buf * 2560;
        const uint32_t* Bb = Bs + buf * 5120;
#pragma unroll
        for (int gi = 0; gi < 2; gi++) {
            const int grp = (gi + warp) & 1;
            const int k8u = grp * 8;
            uint32_t af[2][4], bf[8][2];
#pragma unroll
            for (int mf = 0; mf < 2; mf++) {
                const int rb = warpM * 32 + mf * 16;
                af[mf][0] = Ab[(rb + g)     * 20 + k8u + t];
                af[mf][1] = Ab[(rb + g + 8) * 20 + k8u + t];
                af[mf][2] = Ab[(rb + g)     * 20 + k8u + t + 4];
                af[mf][3] = Ab[(rb + g + 8) * 20 + k8u + t + 4];
            }
#pragma unroll
            for (int nf = 0; nf < 8; nf++) {
                const int nb = warpN * 64 + nf * 8;
                bf[nf][0] = Bb[(nb + g) * 20 + k8u + t];
                bf[nf][1] = Bb[(nb + g) * 20 + k8u + t + 4];
            }
#pragma unroll
            for (int mf = 0; mf < 2; mf++)
#pragma unroll
                for (int nf = 0; nf < 8; nf++)
                    mma16(acc[mf][nf], af[mf], bf[nf]);
        }
        if (it < 15) {
            uint32_t* An = As + (buf ^ 1) * 2560;
#pragma unroll
            for (int i = 0; i < 2; i++) {
                uint32_t* d = An + ar[i] * 20 + au;
                *(uint2*)d = make_uint2(f2h2(a_reg[i].x, a_reg[i].y),
                                        f2h2(a_reg[i].z, a_reg[i].w));
            }
            CP_WAIT0();
        }
        __syncthreads();
    }

    // epilogue: bias + lrelu + store z + per-row sum of squares
    float* part = (float*)As;     // [128][4]
    float zp[4] = {0.f, 0.f, 0.f, 0.f};
#pragma unroll
    for (int mf = 0; mf < 2; mf++) {
#pragma unroll
        for (int nf = 0; nf < 8; nf++) {
            const int rl  = warpM * 32 + mf * 16 + g;
            const int col = warpN * 64 + nf * 8 + t * 2;
            float v0 = acc[mf][nf][0] + bias_s[col];
            float v1 = acc[mf][nf][1] + bias_s[col + 1];
            float v2 = acc[mf][nf][2] + bias_s[col];
            float v3 = acc[mf][nf][3] + bias_s[col + 1];
            v0 = v0 > 0.f ? v0 : NEG_ * v0;
            v1 = v1 > 0.f ? v1 : NEG_ * v1;
            v2 = v2 > 0.f ? v2 : NEG_ * v2;
            v3 = v3 > 0.f ? v3 : NEG_ * v3;
            *(float2*)&dout[Z_OFF + (row0 + rl) * 256 + col] =
                make_float2(v0, v1);
            *(float2*)&dout[Z_OFF + (row0 + rl + 8) * 256 + col] =
                make_float2(v2, v3);
            zp[mf * 2]     += v0 * v0 + v1 * v1;
            zp[mf * 2 + 1] += v2 * v2 + v3 * v3;
        }
    }
#pragma unroll
    for (int j = 0; j < 4; j++) {
        zp[j] += __shfl_xor_sync(0xffffffffu, zp[j], 1);
        zp[j] += __shfl_xor_sync(0xffffffffu, zp[j], 2);
    }
    __syncthreads();
    if (t == 0) {
#pragma unroll
        for (int j = 0; j < 4; j++) {
            const int rl = warpM * 32 + (j >> 1) * 16 + g + (j & 1) * 8;
            part[rl * 4 + warpN] = zp[j];
        }
    }
    __syncthreads();
    if (tid < 128) {
        float s = part[tid * 4] + part[tid * 4 + 1]
                + part[tid * 4 + 2] + part[tid * 4 + 3];
        g_zsq[row0 + tid] = s;
        g_zn[row0 + tid]  = fmaxf(sqrtf(s), COS_EPS_);
    }
}

// ---------------------------------------------------------------------------
// K3 (tf32 mma, measured 24.4us, unchanged): out = z @ ssfn; dist/sim;
// log-softmaxes. dynsmem u32: Bs 10240 | As 2*4096  (=73728 B)
// ---------------------------------------------------------------------------
__global__ void __launch_bounds__(256) smn_k3_tc(float* __restrict__ dout)
{
    extern __shared__ uint32_t dynsmem[];
    uint32_t* Bs = dynsmem;            // 5 n8grp * 32 kk * 64
    uint32_t* As = dynsmem + 10240;    // 2 * 8 tiles * 4 kk * 128
    __shared__ float csq_s[NCLASS_], cn_s[NCLASS_];

    const int tid  = threadIdx.x;
    const int lane = tid & 31, warp = tid >> 5;
    const int g = lane >> 2, t = lane & 3;
    const long row0 = (long)blockIdx.x * 128;
    const float* zg = dout + Z_OFF;

    for (int e = tid; e < NSSF_ * NCLASS_; e += 256) {
        int k = e / NCLASS_, n = e - k * NCLASS_;
        float v = dout[SSFN_OFF + e];
        int kk = k >> 3, kp = k & 7, tt = kp & 3, hi2 = kp >> 2;
        int phys = (((n & 7) * 4 + tt) + kk * 2) & 31;
        Bs[((n >> 3) * 32 + kk) * 64 + phys * 2 + hi2] = f2tf(v);
    }
    if (tid < NCLASS_) { csq_s[tid] = g_csq[tid]; cn_s[tid] = g_cn[tid]; }

    const int ar[4] = { (tid) >> 3, (tid + 256) >> 3,
                        (tid + 512) >> 3, (tid + 768) >> 3 };
    const int ac  = (tid & 7) * 4;
    const int kkt = ac >> 3, hit = (ac >> 2) & 1, rot = kkt * 2;
    float4 a_reg[4];

    auto stageA3 = [&](uint32_t* dstbuf) {
#pragma unroll
        for (int i = 0; i < 4; i++) {
            const int r = ar[i];
            uint32_t* d = dstbuf + (((r >> 4) * 4 + kkt) * 128)
                        + ((r >> 3) & 1) + 2 * hit;
            const int l0 = (r & 7) * 4;
            d[(((l0 + 0) + rot) & 31) * 4] = f2tf(a_reg[i].x);
            d[(((l0 + 1) + rot) & 31) * 4] = f2tf(a_reg[i].y);
            d[(((l0 + 2) + rot) & 31) * 4] = f2tf(a_reg[i].z);
            d[(((l0 + 3) + rot) & 31) * 4] = f2tf(a_reg[i].w);
        }
    };

    float acc[5][4];
#pragma unroll
    for (int nf = 0; nf < 5; nf++)
#pragma unroll
        for (int v = 0; v < 4; v++) acc[nf][v] = 0.f;

#pragma unroll
    for (int i = 0; i < 4; i++)
        a_reg[i] = *(const float4*)(zg + (row0 + ar[i]) * 256 + ac);
    stageA3(As);
    __syncthreads();

    for (int it = 0; it < 8; it++) {
        const int buf = it & 1;
        if (it < 7) {
            const int ks = (it + 1) * 32;
#pragma unroll
            for (int i = 0; i < 4; i++)
                a_reg[i] = *(const float4*)(zg + (row0 + ar[i]) * 256 + ks + ac);
        }
        const uint32_t* Ab = As + buf * 4096;
#pragma unroll
        for (int kk = 0; kk < 4; kk++) {
            const int kkg = it * 4 + kk;
            const int prA = (lane + kk * 2) & 31;
            const int prB = (lane + kkg * 2) & 31;
            uint4 av = *(const uint4*)&Ab[(warp * 4 + kk) * 128 + prA * 4];
#pragma unroll
            for (int nf = 0; nf < 5; nf++) {
                uint2 bv = *(const uint2*)&Bs[(nf * 32 + kkg) * 64 + prB * 2];
                mma8(acc[nf], reinterpret_cast<const uint32_t*>(&av),
                     reinterpret_cast<const uint32_t*>(&bv));
            }
        }
        if (it < 7) stageA3(As + (buf ^ 1) * 4096);
        __syncthreads();
    }

#pragma unroll
    for (int rs = 0; rs < 2; rs++) {
        const long row = row0 + warp * 16 + g + rs * 8;
        const float zsq = g_zsq[row];
        const float zn  = g_zn[row];
        float dv[5][2], sv[5][2], av[5][2];
        float md = -1e30f, ms = -1e30f;
#pragma unroll
        for (int nf = 0; nf < 5; nf++) {
#pragma unroll
            for (int u = 0; u < 2; u++) {
                const int col = nf * 8 + t * 2 + u;
                float a = acc[nf][rs * 2 + u];
                av[nf][u] = a;
                float d = -sqrtf(fmaxf(zsq + csq_s[col] - 2.f * a, 0.f));
                float s = a / (zn * cn_s[col]);
                dv[nf][u] = d; sv[nf][u] = s;
                md = fmaxf(md, d); ms = fmaxf(ms, s);
            }
        }
        md = fmaxf(md, __shfl_xor_sync(0xffffffffu, md, 1));
        md = fmaxf(md, __shfl_xor_sync(0xffffffffu, md, 2));
        ms = fmaxf(ms, __shfl_xor_sync(0xffffffffu, ms, 1));
        ms = fmaxf(ms, __shfl_xor_sync(0xffffffffu, ms, 2));
        float ed = 0.f, es = 0.f;
#pragma unroll
        for (int nf = 0; nf < 5; nf++)
#pragma unroll
            for (int u = 0; u < 2; u++) {
                ed += expf(dv[nf][u] - md);
                es += expf(sv[nf][u] - ms);
            }
        ed += __shfl_xor_sync(0xffffffffu, ed, 1);
        ed += __shfl_xor_sync(0xffffffffu, ed, 2);
        es += __shfl_xor_sync(0xffffffffu, es, 1);
        es += __shfl_xor_sync(0xffffffffu, es, 2);
        const float lse_d = md + logf(ed);
        const float lse_s = ms + logf(es);
#pragma unroll
        for (int nf = 0; nf < 5; nf++) {
            const int col = nf * 8 + t * 2;
            *(float2*)&dout[OUT_OFF + row * NCLASS_ + col] =
                make_float2(av[nf][0], av[nf][1]);
            *(float2*)&dout[LOSS_OFF + row * NCLASS_ + col] = make_float2(
                0.5f * ((dv[nf][0] - lse_d) + (sv[nf][0] - lse_s)),
                0.5f * ((dv[nf][1] - lse_d) + (sv[nf][1] - lse_s)));
        }
    }
}

// ---------------------------------------------------------------------------
extern "C" void kernel_launch(void* const* d_in, const int* in_sizes, int n_in,
                              void* d_out, int out_size)
{
    const float* x      = (const float*)d_in[0];
    const float* W_pre  = (const float*)d_in[1];
    const float* b_pre  = (const float*)d_in[2];
    const float* att    = (const float*)d_in[3];
    const float* W_post = (const float*)d_in[4];
    const float* b_post = (const float*)d_in[5];
    const float* ssf    = (const float*)d_in[6];
    const float* sigma  = (const float*)d_in[7];
    float* dout = (float*)d_out;

    const int K1_SMEM = (768 + 2 * 96 * 20 + 2 * 128 * 20) * 4;   // 38912
    const int K2_SMEM = (2 * 128 * 20 + 2 * 256 * 20) * 4;        // 61440
    const int K3_SMEM = (10240 + 2 * 4096) * 4;                   // 73728
    cudaFuncSetAttribute(smn_k1_tc,
                         cudaFuncAttributeMaxDynamicSharedMemorySize, K1_SMEM);
    cudaFuncSetAttribute(smn_k2_tc,
                         cudaFuncAttributeMaxDynamicSharedMemorySize, K2_SMEM);
    cudaFuncSetAttribute(smn_k3_tc,
                         cudaFuncAttributeMaxDynamicSharedMemorySize, K3_SMEM);

    smn_wcvt_ssf<<<1537, 256>>>(W_pre, W_post, ssf, sigma, dout);
    smn_k1_tc<<<dim3(4, NN / 16), 256, K1_SMEM>>>(x, b_pre, att);
    smn_k2_tc<<<NN / 128, 512, K2_SMEM>>>(b_post, dout);
    smn_k3_tc<<<NN / 128, 256, K3_SMEM>>>(dout);
}

// round 12
// speedup vs baseline: 1.7239x; 1.1442x over previous
#include <cuda_runtime.h>
#include <cuda_fp16.h>
#include <math.h>
#include <stdint.h>

#define NN      32768
#define NHOPS   6
#define NFEAT_  512
#define NSSF_   256
#define NCLASS_ 40
#define NEG_    0.2f
#define COS_EPS_ 1e-6f

// output layout (flattened tuple, element offsets)
#define OUT_OFF   0
#define SSFN_OFF  (NN*NCLASS_)                    // 1310720
#define Z_OFF     (SSFN_OFF + NSSF_*NCLASS_)      // 1320960
#define LOSS_OFF  (Z_OFF + NN*NSSF_)              // 9709568
#define SIGMA_OFF (LOSS_OFF + NN*NCLASS_)         // 11020288

// scratch (static device globals — no runtime allocation)
__device__ float g_z1[(long)NN * 512];
__device__ float g_zsq[NN];
__device__ float g_zn[NN];
__device__ float g_csq[NCLASS_];
__device__ float g_cn[NCLASS_];
__device__ __half g_Wp_h[512 * 512];   // W_pre fp16
__device__ __half g_Wq_h[256 * 512];   // W_post fp16

// ---------------------------------------------------------------------------
// helpers
// ---------------------------------------------------------------------------
__device__ __forceinline__ uint32_t f2tf(float x) {
    uint32_t y;
    asm("cvt.rna.tf32.f32 %0, %1;" : "=r"(y) : "f"(x));
    return y;
}
__device__ __forceinline__ uint32_t f2h2(float a, float b) {
    __half2 h = __floats2half2_rn(a, b);
    return *reinterpret_cast<uint32_t*>(&h);
}
__device__ __forceinline__ void mma8(float c[4], const uint32_t a[4],
                                     const uint32_t b[2]) {
    asm volatile(
        "mma.sync.aligned.m16n8k8.row.col.f32.tf32.tf32.f32 "
        "{%0,%1,%2,%3}, {%4,%5,%6,%7}, {%8,%9}, {%0,%1,%2,%3};\n"
        : "+f"(c[0]), "+f"(c[1]), "+f"(c[2]), "+f"(c[3])
        : "r"(a[0]), "r"(a[1]), "r"(a[2]), "r"(a[3]), "r"(b[0]), "r"(b[1]));
}
__device__ __forceinline__ void mma16(float c[4], const uint32_t a[4],
                                      const uint32_t b[2]) {
    asm volatile(
        "mma.sync.aligned.m16n8k16.row.col.f32.f16.f16.f32 "
        "{%0,%1,%2,%3}, {%4,%5,%6,%7}, {%8,%9}, {%0,%1,%2,%3};\n"
        : "+f"(c[0]), "+f"(c[1]), "+f"(c[2]), "+f"(c[3])
        : "r"(a[0]), "r"(a[1]), "r"(a[2]), "r"(a[3]), "r"(b[0]), "r"(b[1]));
}
__device__ __forceinline__ uint32_t smem_u32p(const void* p) {
    uint32_t a;
    asm("{ .reg .u64 t; cvta.to.shared.u64 t, %1; cvt.u32.u64 %0, t; }"
        : "=r"(a) : "l"(p));
    return a;
}
__device__ __forceinline__ void cp16(uint32_t saddr, const void* g) {
    asm volatile("cp.async.ca.shared.global [%0], [%1], 16;"
                 :: "r"(saddr), "l"(g));
}
#define CP_COMMIT() asm volatile("cp.async.commit_group;")
#define CP_WAIT0()  asm volatile("cp.async.wait_group 0;")

// ---------------------------------------------------------------------------
// Kw: weight fp16 pre-convert (blocks 0..1535) + K0 ssf work (block 1536).
// ---------------------------------------------------------------------------
__global__ void __launch_bounds__(256) smn_wcvt_ssf(
    const float* __restrict__ Wp, const float* __restrict__ Wq,
    const float* __restrict__ ssf, const float* __restrict__ sigma,
    float* __restrict__ dout)
{
    __shared__ float fbuf[NSSF_ * NCLASS_];
    __shared__ int   cnt_s[256];
    const int tid = threadIdx.x;

    if (blockIdx.x < 1536) {
        int i = blockIdx.x * 256 + tid;
        if (i < 512 * 512) {
            g_Wp_h[i] = __float2half_rn(Wp[i]);
        } else {
            int j = i - 512 * 512;
            if (j < 256 * 512) g_Wq_h[j] = __float2half_rn(Wq[j]);
        }
        return;
    }

    unsigned* keys = reinterpret_cast<unsigned*>(fbuf);
    for (int i = tid; i < NSSF_ * NCLASS_; i += 256)
        keys[i] = __float_as_uint(fabsf(ssf[i]));
    __syncthreads();

    unsigned lo = 0u, hi = 0x7f800000u;
    while (lo < hi) {
        unsigned mid = (lo + hi) >> 1;
        int c = 0;
        for (int i = tid; i < NSSF_ * NCLASS_; i += 256) c += (keys[i] <= mid);
        cnt_s[tid] = c;
        __syncthreads();
        for (int s = 128; s > 0; s >>= 1) {
            if (tid < s) cnt_s[tid] += cnt_s[tid + s];
            __syncthreads();
        }
        int total = cnt_s[0];
        __syncthreads();
        if (total >= 5121) hi = mid; else lo = mid + 1;
    }
    const float thr = __uint_as_float(lo);

    float row[NCLASS_];
    float rs = 0.f;
    const float* srow = ssf + tid * NCLASS_;
#pragma unroll
    for (int j = 0; j < NCLASS_; j++) {
        float v = srow[j];
        v = (fabsf(v) >= thr) ? v : 0.f;
        row[j] = v;
        rs += fabsf(v);
    }
    const float inv = 1.f / fmaxf(rs, 1e-12f);
#pragma unroll
    for (int j = 0; j < NCLASS_; j++) {
        float v = row[j] * inv;
        dout[SSFN_OFF + tid * NCLASS_ + j] = v;
        fbuf[tid * NCLASS_ + j] = v;
    }
    __syncthreads();

    if (tid < NCLASS_) {
        float c2 = 0.f;
        for (int i = 0; i < NSSF_; i++) {
            float v = fbuf[i * NCLASS_ + tid];
            c2 += v * v;
        }
        g_csq[tid] = c2;
        g_cn[tid]  = fmaxf(sqrtf(c2), COS_EPS_);
    }
    if (tid < 2) dout[SIGMA_OFF + tid] = sigma[tid];
}

// ---------------------------------------------------------------------------
// K1 (fp16, B-RESIDENT): W slice (128 cols x 512 k fp16 = 130KB) loaded into
// smem ONCE per block; block loops over ~7 node-tiles of M=192 (32 nodes),
// K in 64-chunks, double-buffered A. 512 threads, 16 warps (4M x 4N),
// warp tile 48x32. smem u32: atts 768 | Bres [128][260] | A[2][192][36]
// = 768 + 33280 + 13824 = 47872 u32 = 191488 B. 1 block/SM.
// ---------------------------------------------------------------------------
#define K1_TILES 1024      // 196608 rows / 192

__global__ void __launch_bounds__(512) smn_k1_tc(
    const float* __restrict__ x,
    const float* __restrict__ bp, const float* __restrict__ att)
{
    extern __shared__ uint32_t dynsmem[];
    float*    atts = (float*)dynsmem;            // 768
    uint32_t* Bres = dynsmem + 768;              // 128 * 260
    uint32_t* As   = Bres + 128 * 260;           // 2 * 192 * 36

    const int tid  = threadIdx.x;
    const int lane = tid & 31, warp = tid >> 5;
    const int warpM = warp >> 2, warpN = warp & 3;   // 4 x 4
    const int g = lane >> 2, t = lane & 3;
    const int col0 = blockIdx.x * 128;

    for (int i = tid; i < 768; i += 512)
        atts[i] = att[2 * blockIdx.x * 384 + i];

    // ---- load resident B slice once: 128 rows x 256 u32, 16 cp16/thread ----
#pragma unroll
    for (int i = 0; i < 16; i++) {
        int s  = tid + i * 512;
        int n  = s >> 6;             // 64 16B-slots per row
        int ks = s & 63;
        cp16(smem_u32p(&Bres[n * 260 + ks * 4]),
             g_Wp_h + (size_t)(col0 + n) * 512 + ks * 8);
    }
    CP_COMMIT();
    CP_WAIT0();
    __syncthreads();

    // A staging indices: 192 rows x 16 float4/row = 3072 slots, 6 per thread
    int arr[6], acc4[6];
#pragma unroll
    for (int i = 0; i < 6; i++) {
        int idx = tid + i * 512;
        arr[i]  = idx >> 4;
        acc4[i] = (idx & 15) * 4;    // float offset within 64-k window
    }

    for (int tile = blockIdx.y; tile < K1_TILES; tile += gridDim.y) {
        const long row0 = (long)tile * 192;
        const int node0 = tile * 32;

        float acc[3][4][4];
#pragma unroll
        for (int mf = 0; mf < 3; mf++)
#pragma unroll
            for (int nf = 0; nf < 4; nf++)
#pragma unroll
                for (int v = 0; v < 4; v++) acc[mf][nf][v] = 0.f;

        // stage A chunk 0
        float4 a_reg[6];
#pragma unroll
        for (int i = 0; i < 6; i++)
            a_reg[i] = *(const float4*)(x + (row0 + arr[i]) * 512 + acc4[i]);
#pragma unroll
        for (int i = 0; i < 6; i++) {
            uint32_t* d = As + arr[i] * 36 + (acc4[i] >> 1);
            *(uint2*)d = make_uint2(f2h2(a_reg[i].x, a_reg[i].y),
                                    f2h2(a_reg[i].z, a_reg[i].w));
        }
        __syncthreads();

        for (int it = 0; it < 8; it++) {
            const int buf = it & 1;
            if (it < 7) {
                const int ks = (it + 1) * 64;
#pragma unroll
                for (int i = 0; i < 6; i++)
                    a_reg[i] = *(const float4*)(x + (row0 + arr[i]) * 512
                                                + ks + acc4[i]);
            }
            const uint32_t* Ab = As + buf * 6912;
            const uint32_t* Bb = Bres + it * 32;   // k64 chunk base (u32)
            // 4 k16 groups, per-warp rotated
#pragma unroll
            for (int gi = 0; gi < 4; gi++) {
                const int grp = (gi + warp) & 3;
                const int aku = grp * 8;           // A u32 offset of k16 group
                const int bku = grp * 8;           // B u32 offset within chunk
                uint32_t af[3][4], bf[4][2];
#pragma unroll
                for (int mf = 0; mf < 3; mf++) {
                    const int rb = warpM * 48 + mf * 16;
                    af[mf][0] = Ab[(rb + g)     * 36 + aku + t];
                    af[mf][1] = Ab[(rb + g + 8) * 36 + aku + t];
                    af[mf][2] = Ab[(rb + g)     * 36 + aku + t + 4];
                    af[mf][3] = Ab[(rb + g + 8) * 36 + aku + t + 4];
                }
#pragma unroll
                for (int nf = 0; nf < 4; nf++) {
                    const int nb = warpN * 32 + nf * 8;
                    bf[nf][0] = Bb[(nb + g) * 260 + bku + t];
                    bf[nf][1] = Bb[(nb + g) * 260 + bku + t + 4];
                }
#pragma unroll
                for (int mf = 0; mf < 3; mf++)
#pragma unroll
                    for (int nf = 0; nf < 4; nf++)
                        mma16(acc[mf][nf], af[mf], bf[nf]);
            }
            if (it < 7) {
                uint32_t* An = As + (buf ^ 1) * 6912;
#pragma unroll
                for (int i = 0; i < 6; i++) {
                    uint32_t* d = An + arr[i] * 36 + (acc4[i] >> 1);
                    *(uint2*)d = make_uint2(f2h2(a_reg[i].x, a_reg[i].y),
                                            f2h2(a_reg[i].z, a_reg[i].w));
                }
            }
            __syncthreads();
        }

        // epilogue: two 64-col halves; Cs [192][68] reuses A region
        float* Cs = (float*)As;
#pragma unroll
        for (int half = 0; half < 2; half++) {
            if ((warpN >> 1) == half) {
#pragma unroll
                for (int mf = 0; mf < 3; mf++)
#pragma unroll
                    for (int nf = 0; nf < 4; nf++) {
                        const int r  = warpM * 48 + mf * 16 + g;
                        const int cc = (warpN & 1) * 32 + nf * 8 + t * 2;
                        Cs[r * 68 + cc]           = acc[mf][nf][0];
                        Cs[r * 68 + cc + 1]       = acc[mf][nf][1];
                        Cs[(r + 8) * 68 + cc]     = acc[mf][nf][2];
                        Cs[(r + 8) * 68 + cc + 1] = acc[mf][nf][3];
                    }
            }
            __syncthreads();
            {
                const int ty = tid >> 4;        // 0..31 (node within tile)
                const int tx = tid & 15;
                const int node = node0 + ty;
                const int cg = half * 64 + tx * 4;
                float4 b4 = *(const float4*)(bp + col0 + cg);
                float bv[4] = {b4.x, b4.y, b4.z, b4.w};
                float zr[4];
#pragma unroll
                for (int c = 0; c < 4; c++) {
                    float h[NHOPS], am[NHOPS], s[NHOPS];
#pragma unroll
                    for (int r = 0; r < NHOPS; r++) {
                        float v = Cs[(ty * 6 + r) * 68 + tx * 4 + c] + bv[c];
                        v = v > 0.f ? v : NEG_ * v;
                        h[r]  = v;
                        am[r] = v * atts[half * 384 + r * 64 + tx * 4 + c];
                    }
                    float m = -1e30f;
#pragma unroll
                    for (int r = 0; r < NHOPS; r++) {
                        float u = am[0] + am[r];
                        u = u > 0.f ? u : NEG_ * u;
                        s[r] = u;
                        m = fmaxf(m, u);
                    }
                    float den = 0.f, num = 0.f;
#pragma unroll
                    for (int r = 0; r < NHOPS; r++) {
                        float w = expf(s[r] - m);
                        den += w;
                        num += h[r] * w;
                    }
                    zr[c] = num / den;
                }
                *(float4*)&g_z1[(long)node * 512 + col0 + cg] =
                    make_float4(zr[0], zr[1], zr[2], zr[3]);
            }
            __syncthreads();
        }
    }
}

// ---------------------------------------------------------------------------
// K2 (fp16 m16n8k16, round-11 version): z = lrelu(z1 @ W_post^T + b) + zsq/zn.
// Block 128x256, 512 threads, warp tile 32x64. smem = 61440 B.
// ---------------------------------------------------------------------------
__global__ void __launch_bounds__(512) smn_k2_tc(
    const float* __restrict__ bq, float* __restrict__ dout)
{
    extern __shared__ uint32_t dynsmem[];
    uint32_t* As = dynsmem;                   // 2 * 128*20
    uint32_t* Bs = As + 2 * 128 * 20;         // 2 * 256*20
    __shared__ float bias_s[256];

    const int tid  = threadIdx.x;
    const int lane = tid & 31, warp = tid >> 5;
    const int warpM = warp >> 2, warpN = warp & 3;
    const int g = lane >> 2, t = lane & 3;
    const long row0 = (long)blockIdx.x * 128;

    if (tid < 256) bias_s[tid] = bq[tid];

    const int ar[2] = { (tid + 0) >> 3, (tid + 512) >> 3 };
    const int ac    = (tid & 7) * 4;
    const int au    = ac >> 1;
    float4 a_reg[2];

    uint32_t bsa[2];
    const __half* wsrc[2];
#pragma unroll
    for (int i = 0; i < 2; i++) {
        int idx = tid + i * 512;
        int n   = idx >> 2;
        int kh  = (idx & 3) * 8;
        bsa[i]  = smem_u32p(&Bs[n * 20 + (kh >> 1)]);
        wsrc[i] = g_Wq_h + (long)n * 512 + kh;
    }
    const uint32_t bufB_bytes = 5120 * 4;

    float acc[2][8][4];
#pragma unroll
    for (int mf = 0; mf < 2; mf++)
#pragma unroll
        for (int nf = 0; nf < 8; nf++)
#pragma unroll
            for (int v = 0; v < 4; v++) acc[mf][nf][v] = 0.f;

#pragma unroll
    for (int i = 0; i < 2; i++) cp16(bsa[i], wsrc[i]);
    CP_COMMIT();
#pragma unroll
    for (int i = 0; i < 2; i++)
        a_reg[i] = *(const float4*)(g_z1 + (row0 + ar[i]) * 512 + ac);
#pragma unroll
    for (int i = 0; i < 2; i++) {
        uint32_t* d = As + ar[i] * 20 + au;
        *(uint2*)d = make_uint2(f2h2(a_reg[i].x, a_reg[i].y),
                                f2h2(a_reg[i].z, a_reg[i].w));
    }
    CP_WAIT0();
    __syncthreads();

    for (int it = 0; it < 16; it++) {
        const int buf = it & 1;
        if (it < 15) {
            const int ks = (it + 1) * 32;
#pragma unroll
            for (int i = 0; i < 2; i++)
                cp16(bsa[i] + (buf ^ 1) * bufB_bytes, wsrc[i] + ks);
            CP_COMMIT();
#pragma unroll
            for (int i = 0; i < 2; i++)
                a_reg[i] = *(const float4*)(g_z1 + (row0 + ar[i]) * 512 + ks + ac);
        }
        const uint32_t* Ab = As + buf * 2560;
        const uint32_t* Bb = Bs + buf * 5120;
#pragma unroll
        for (int gi = 0; gi < 2; gi++) {
            const int grp = (gi + warp) & 1;
            const int k8u = grp * 8;
            uint32_t af[2][4], bf[8][2];
#pragma unroll
            for (int mf = 0; mf < 2; mf++) {
                const int rb = warpM * 32 + mf * 16;
                af[mf][0] = Ab[(rb + g)     * 20 + k8u + t];
                af[mf][1] = Ab[(rb + g + 8) * 20 + k8u + t];
                af[mf][2] = Ab[(rb + g)     * 20 + k8u + t + 4];
                af[mf][3] = Ab[(rb + g + 8) * 20 + k8u + t + 4];
            }
#pragma unroll
            for (int nf = 0; nf < 8; nf++) {
                const int nb = warpN * 64 + nf * 8;
                bf[nf][0] = Bb[(nb + g) * 20 + k8u + t];
                bf[nf][1] = Bb[(nb + g) * 20 + k8u + t + 4];
            }
#pragma unroll
            for (int mf = 0; mf < 2; mf++)
#pragma unroll
                for (int nf = 0; nf < 8; nf++)
                    mma16(acc[mf][nf], af[mf], bf[nf]);
        }
        if (it < 15) {
            uint32_t* An = As + (buf ^ 1) * 2560;
#pragma unroll
            for (int i = 0; i < 2; i++) {
                uint32_t* d = An + ar[i] * 20 + au;
                *(uint2*)d = make_uint2(f2h2(a_reg[i].x, a_reg[i].y),
                                        f2h2(a_reg[i].z, a_reg[i].w));
            }
            CP_WAIT0();
        }
        __syncthreads();
    }

    float* part = (float*)As;     // [128][4]
    float zp[4] = {0.f, 0.f, 0.f, 0.f};
#pragma unroll
    for (int mf = 0; mf < 2; mf++) {
#pragma unroll
        for (int nf = 0; nf < 8; nf++) {
            const int rl  = warpM * 32 + mf * 16 + g;
            const int col = warpN * 64 + nf * 8 + t * 2;
            float v0 = acc[mf][nf][0] + bias_s[col];
            float v1 = acc[mf][nf][1] + bias_s[col + 1];
            float v2 = acc[mf][nf][2] + bias_s[col];
            float v3 = acc[mf][nf][3] + bias_s[col + 1];
            v0 = v0 > 0.f ? v0 : NEG_ * v0;
            v1 = v1 > 0.f ? v1 : NEG_ * v1;
            v2 = v2 > 0.f ? v2 : NEG_ * v2;
            v3 = v3 > 0.f ? v3 : NEG_ * v3;
            *(float2*)&dout[Z_OFF + (row0 + rl) * 256 + col] =
                make_float2(v0, v1);
            *(float2*)&dout[Z_OFF + (row0 + rl + 8) * 256 + col] =
                make_float2(v2, v3);
            zp[mf * 2]     += v0 * v0 + v1 * v1;
            zp[mf * 2 + 1] += v2 * v2 + v3 * v3;
        }
    }
#pragma unroll
    for (int j = 0; j < 4; j++) {
        zp[j] += __shfl_xor_sync(0xffffffffu, zp[j], 1);
        zp[j] += __shfl_xor_sync(0xffffffffu, zp[j], 2);
    }
    __syncthreads();
    if (t == 0) {
#pragma unroll
        for (int j = 0; j < 4; j++) {
            const int rl = warpM * 32 + (j >> 1) * 16 + g + (j & 1) * 8;
            part[rl * 4 + warpN] = zp[j];
        }
    }
    __syncthreads();
    if (tid < 128) {
        float s = part[tid * 4] + part[tid * 4 + 1]
                + part[tid * 4 + 2] + part[tid * 4 + 3];
        g_zsq[row0 + tid] = s;
        g_zn[row0 + tid]  = fmaxf(sqrtf(s), COS_EPS_);
    }
}

// ---------------------------------------------------------------------------
// K3 (tf32 mma, unchanged, ~24us)
// ---------------------------------------------------------------------------
__global__ void __launch_bounds__(256) smn_k3_tc(float* __restrict__ dout)
{
    extern __shared__ uint32_t dynsmem[];
    uint32_t* Bs = dynsmem;
    uint32_t* As = dynsmem + 10240;
    __shared__ float csq_s[NCLASS_], cn_s[NCLASS_];

    const int tid  = threadIdx.x;
    const int lane = tid & 31, warp = tid >> 5;
    const int g = lane >> 2, t = lane & 3;
    const long row0 = (long)blockIdx.x * 128;
    const float* zg = dout + Z_OFF;

    for (int e = tid; e < NSSF_ * NCLASS_; e += 256) {
        int k = e / NCLASS_, n = e - k * NCLASS_;
        float v = dout[SSFN_OFF + e];
        int kk = k >> 3, kp = k & 7, tt = kp & 3, hi2 = kp >> 2;
        int phys = (((n & 7) * 4 + tt) + kk * 2) & 31;
        Bs[((n >> 3) * 32 + kk) * 64 + phys * 2 + hi2] = f2tf(v);
    }
    if (tid < NCLASS_) { csq_s[tid] = g_csq[tid]; cn_s[tid] = g_cn[tid]; }

    const int ar[4] = { (tid) >> 3, (tid + 256) >> 3,
                        (tid + 512) >> 3, (tid + 768) >> 3 };
    const int ac  = (tid & 7) * 4;
    const int kkt = ac >> 3, hit = (ac >> 2) & 1, rot = kkt * 2;
    float4 a_reg[4];

    auto stageA3 = [&](uint32_t* dstbuf) {
#pragma unroll
        for (int i = 0; i < 4; i++) {
            const int r = ar[i];
            uint32_t* d = dstbuf + (((r >> 4) * 4 + kkt) * 128)
                        + ((r >> 3) & 1) + 2 * hit;
            const int l0 = (r & 7) * 4;
            d[(((l0 + 0) + rot) & 31) * 4] = f2tf(a_reg[i].x);
            d[(((l0 + 1) + rot) & 31) * 4] = f2tf(a_reg[i].y);
            d[(((l0 + 2) + rot) & 31) * 4] = f2tf(a_reg[i].z);
            d[(((l0 + 3) + rot) & 31) * 4] = f2tf(a_reg[i].w);
        }
    };

    float acc[5][4];
#pragma unroll
    for (int nf = 0; nf < 5; nf++)
#pragma unroll
        for (int v = 0; v < 4; v++) acc[nf][v] = 0.f;

#pragma unroll
    for (int i = 0; i < 4; i++)
        a_reg[i] = *(const float4*)(zg + (row0 + ar[i]) * 256 + ac);
    stageA3(As);
    __syncthreads();

    for (int it = 0; it < 8; it++) {
        const int buf = it & 1;
        if (it < 7) {
            const int ks = (it + 1) * 32;
#pragma unroll
            for (int i = 0; i < 4; i++)
                a_reg[i] = *(const float4*)(zg + (row0 + ar[i]) * 256 + ks + ac);
        }
        const uint32_t* Ab = As + buf * 4096;
#pragma unroll
        for (int kk = 0; kk < 4; kk++) {
            const int kkg = it * 4 + kk;
            const int prA = (lane + kk * 2) & 31;
            const int prB = (lane + kkg * 2) & 31;
            uint4 av = *(const uint4*)&Ab[(warp * 4 + kk) * 128 + prA * 4];
#pragma unroll
            for (int nf = 0; nf < 5; nf++) {
                uint2 bv = *(const uint2*)&Bs[(nf * 32 + kkg) * 64 + prB * 2];
                mma8(acc[nf], reinterpret_cast<const uint32_t*>(&av),
                     reinterpret_cast<const uint32_t*>(&bv));
            }
        }
        if (it < 7) stageA3(As + (buf ^ 1) * 4096);
        __syncthreads();
    }

#pragma unroll
    for (int rs = 0; rs < 2; rs++) {
        const long row = row0 + warp * 16 + g + rs * 8;
        const float zsq = g_zsq[row];
        const float zn  = g_zn[row];
        float dv[5][2], sv[5][2], av[5][2];
        float md = -1e30f, ms = -1e30f;
#pragma unroll
        for (int nf = 0; nf < 5; nf++) {
#pragma unroll
            for (int u = 0; u < 2; u++) {
                const int col = nf * 8 + t * 2 + u;
                float a = acc[nf][rs * 2 + u];
                av[nf][u] = a;
                float d = -sqrtf(fmaxf(zsq + csq_s[col] - 2.f * a, 0.f));
                float s = a / (zn * cn_s[col]);
                dv[nf][u] = d; sv[nf][u] = s;
                md = fmaxf(md, d); ms = fmaxf(ms, s);
            }
        }
        md = fmaxf(md, __shfl_xor_sync(0xffffffffu, md, 1));
        md = fmaxf(md, __shfl_xor_sync(0xffffffffu, md, 2));
        ms = fmaxf(ms, __shfl_xor_sync(0xffffffffu, ms, 1));
        ms = fmaxf(ms, __shfl_xor_sync(0xffffffffu, ms, 2));
        float ed = 0.f, es = 0.f;
#pragma unroll
        for (int nf = 0; nf < 5; nf++)
#pragma unroll
            for (int u = 0; u < 2; u++) {
                ed += expf(dv[nf][u] - md);
                es += expf(sv[nf][u] - ms);
            }
        ed += __shfl_xor_sync(0xffffffffu, ed, 1);
        ed += __shfl_xor_sync(0xffffffffu, ed, 2);
        es += __shfl_xor_sync(0xffffffffu, es, 1);
        es += __shfl_xor_sync(0xffffffffu, es, 2);
        const float lse_d = md + logf(ed);
        const float lse_s = ms + logf(es);
#pragma unroll
        for (int nf = 0; nf < 5; nf++) {
            const int col = nf * 8 + t * 2;
            *(float2*)&dout[OUT_OFF + row * NCLASS_ + col] =
                make_float2(av[nf][0], av[nf][1]);
            *(float2*)&dout[LOSS_OFF + row * NCLASS_ + col] = make_float2(
                0.5f * ((dv[nf][0] - lse_d) + (sv[nf][0] - lse_s)),
                0.5f * ((dv[nf][1] - lse_d) + (sv[nf][1] - lse_s)));
        }
    }
}

// ---------------------------------------------------------------------------
extern "C" void kernel_launch(void* const* d_in, const int* in_sizes, int n_in,
                              void* d_out, int out_size)
{
    const float* x      = (const float*)d_in[0];
    const float* W_pre  = (const float*)d_in[1];
    const float* b_pre  = (const float*)d_in[2];
    const float* att    = (const float*)d_in[3];
    const float* W_post = (const float*)d_in[4];
    const float* b_post = (const float*)d_in[5];
    const float* ssf    = (const float*)d_in[6];
    const float* sigma  = (const float*)d_in[7];
    float* dout = (float*)d_out;

    const int K1_SMEM = (768 + 128 * 260 + 2 * 192 * 36) * 4;    // 191488
    const int K2_SMEM = (2 * 128 * 20 + 2 * 256 * 20) * 4;       // 61440
    const int K3_SMEM = (10240 + 2 * 4096) * 4;                  // 73728
    cudaFuncSetAttribute(smn_k1_tc,
                         cudaFuncAttributeMaxDynamicSharedMemorySize, K1_SMEM);
    cudaFuncSetAttribute(smn_k2_tc,
                         cudaFuncAttributeMaxDynamicSharedMemorySize, K2_SMEM);
    cudaFuncSetAttribute(smn_k3_tc,
                         cudaFuncAttributeMaxDynamicSharedMemorySize, K3_SMEM);

    smn_wcvt_ssf<<<1537, 256>>>(W_pre, W_post, ssf, sigma, dout);
    smn_k1_tc<<<dim3(4, 148), 512, K1_SMEM>>>(x, b_pre, att);
    smn_k2_tc<<<NN / 128, 512, K2_SMEM>>>(b_post, dout);
    smn_k3_tc<<<NN / 128, 256, K3_SMEM>>>(dout);
}

// round 13
// speedup vs baseline: 1.7989x; 1.0435x over previous
#include <cuda_runtime.h>
#include <cuda_fp16.h>
#include <math.h>
#include <stdint.h>

#define NN      32768
#define NHOPS   6
#define NFEAT_  512
#define NSSF_   256
#define NCLASS_ 40
#define NEG_    0.2f
#define COS_EPS_ 1e-6f

// output layout (flattened tuple, element offsets)
#define OUT_OFF   0
#define SSFN_OFF  (NN*NCLASS_)                    // 1310720
#define Z_OFF     (SSFN_OFF + NSSF_*NCLASS_)      // 1320960
#define LOSS_OFF  (Z_OFF + NN*NSSF_)              // 9709568
#define SIGMA_OFF (LOSS_OFF + NN*NCLASS_)         // 11020288

// scratch (static device globals — no runtime allocation)
__device__ float g_z1[(long)NN * 512];
__device__ float g_zsq[NN];
__device__ float g_zn[NN];
__device__ float g_csq[NCLASS_];
__device__ float g_cn[NCLASS_];
__device__ __half g_Wp_h[512 * 512];   // W_pre fp16
__device__ __half g_Wq_h[256 * 512];   // W_post fp16

// ---------------------------------------------------------------------------
// helpers
// ---------------------------------------------------------------------------
__device__ __forceinline__ uint32_t f2tf(float x) {
    uint32_t y;
    asm("cvt.rna.tf32.f32 %0, %1;" : "=r"(y) : "f"(x));
    return y;
}
__device__ __forceinline__ uint32_t f2h2(float a, float b) {
    __half2 h = __floats2half2_rn(a, b);
    return *reinterpret_cast<uint32_t*>(&h);
}
__device__ __forceinline__ void mma8(float c[4], const uint32_t a[4],
                                     const uint32_t b[2]) {
    asm volatile(
        "mma.sync.aligned.m16n8k8.row.col.f32.tf32.tf32.f32 "
        "{%0,%1,%2,%3}, {%4,%5,%6,%7}, {%8,%9}, {%0,%1,%2,%3};\n"
        : "+f"(c[0]), "+f"(c[1]), "+f"(c[2]), "+f"(c[3])
        : "r"(a[0]), "r"(a[1]), "r"(a[2]), "r"(a[3]), "r"(b[0]), "r"(b[1]));
}
__device__ __forceinline__ void mma16(float c[4], const uint32_t a[4],
                                      const uint32_t b[2]) {
    asm volatile(
        "mma.sync.aligned.m16n8k16.row.col.f32.f16.f16.f32 "
        "{%0,%1,%2,%3}, {%4,%5,%6,%7}, {%8,%9}, {%0,%1,%2,%3};\n"
        : "+f"(c[0]), "+f"(c[1]), "+f"(c[2]), "+f"(c[3])
        : "r"(a[0]), "r"(a[1]), "r"(a[2]), "r"(a[3]), "r"(b[0]), "r"(b[1]));
}
__device__ __forceinline__ void ldsm4(uint32_t& r0, uint32_t& r1,
                                      uint32_t& r2, uint32_t& r3,
                                      uint32_t addr) {
    asm volatile(
        "ldmatrix.sync.aligned.m8n8.x4.shared.b16 {%0,%1,%2,%3}, [%4];"
        : "=r"(r0), "=r"(r1), "=r"(r2), "=r"(r3) : "r"(addr));
}
__device__ __forceinline__ uint32_t smem_u32p(const void* p) {
    uint32_t a;
    asm("{ .reg .u64 t; cvta.to.shared.u64 t, %1; cvt.u32.u64 %0, t; }"
        : "=r"(a) : "l"(p));
    return a;
}
__device__ __forceinline__ void cp16(uint32_t saddr, const void* g) {
    asm volatile("cp.async.ca.shared.global [%0], [%1], 16;"
                 :: "r"(saddr), "l"(g));
}
#define CP_COMMIT() asm volatile("cp.async.commit_group;")
#define CP_WAIT0()  asm volatile("cp.async.wait_group 0;")

// ---------------------------------------------------------------------------
// Kw: weight fp16 pre-convert (blocks 0..1535) + K0 ssf work (block 1536).
// ---------------------------------------------------------------------------
__global__ void __launch_bounds__(256) smn_wcvt_ssf(
    const float* __restrict__ Wp, const float* __restrict__ Wq,
    const float* __restrict__ ssf, const float* __restrict__ sigma,
    float* __restrict__ dout)
{
    __shared__ float fbuf[NSSF_ * NCLASS_];
    __shared__ int   cnt_s[256];
    const int tid = threadIdx.x;

    if (blockIdx.x < 1536) {
        int i = blockIdx.x * 256 + tid;
        if (i < 512 * 512) {
            g_Wp_h[i] = __float2half_rn(Wp[i]);
        } else {
            int j = i - 512 * 512;
            if (j < 256 * 512) g_Wq_h[j] = __float2half_rn(Wq[j]);
        }
        return;
    }

    unsigned* keys = reinterpret_cast<unsigned*>(fbuf);
    for (int i = tid; i < NSSF_ * NCLASS_; i += 256)
        keys[i] = __float_as_uint(fabsf(ssf[i]));
    __syncthreads();

    unsigned lo = 0u, hi = 0x7f800000u;
    while (lo < hi) {
        unsigned mid = (lo + hi) >> 1;
        int c = 0;
        for (int i = tid; i < NSSF_ * NCLASS_; i += 256) c += (keys[i] <= mid);
        cnt_s[tid] = c;
        __syncthreads();
        for (int s = 128; s > 0; s >>= 1) {
            if (tid < s) cnt_s[tid] += cnt_s[tid + s];
            __syncthreads();
        }
        int total = cnt_s[0];
        __syncthreads();
        if (total >= 5121) hi = mid; else lo = mid + 1;
    }
    const float thr = __uint_as_float(lo);

    float row[NCLASS_];
    float rs = 0.f;
    const float* srow = ssf + tid * NCLASS_;
#pragma unroll
    for (int j = 0; j < NCLASS_; j++) {
        float v = srow[j];
        v = (fabsf(v) >= thr) ? v : 0.f;
        row[j] = v;
        rs += fabsf(v);
    }
    const float inv = 1.f / fmaxf(rs, 1e-12f);
#pragma unroll
    for (int j = 0; j < NCLASS_; j++) {
        float v = row[j] * inv;
        dout[SSFN_OFF + tid * NCLASS_ + j] = v;
        fbuf[tid * NCLASS_ + j] = v;
    }
    __syncthreads();

    if (tid < NCLASS_) {
        float c2 = 0.f;
        for (int i = 0; i < NSSF_; i++) {
            float v = fbuf[i * NCLASS_ + tid];
            c2 += v * v;
        }
        g_csq[tid] = c2;
        g_cn[tid]  = fmaxf(sqrtf(c2), COS_EPS_);
    }
    if (tid < 2) dout[SIGMA_OFF + tid] = sigma[tid];
}

// ---------------------------------------------------------------------------
// K1 (fp16, B-resident, ldmatrix fragments): W slice resident in smem;
// block loops over node-tiles of M=192 (32 nodes), K in 64-chunks,
// double-buffered A. 512 threads, 16 warps (4M x 4N), warp tile 48x32.
// smem u32: atts 768 | Bres [128][260] | A[2][192][36] = 191488 B. 1 blk/SM.
// ---------------------------------------------------------------------------
#define K1_TILES 1024      // 196608 rows / 192

__global__ void __launch_bounds__(512) smn_k1_tc(
    const float* __restrict__ x,
    const float* __restrict__ bp, const float* __restrict__ att)
{
    extern __shared__ uint32_t dynsmem[];
    float*    atts = (float*)dynsmem;            // 768
    uint32_t* Bres = dynsmem + 768;              // 128 * 260
    uint32_t* As   = Bres + 128 * 260;           // 2 * 192 * 36

    const int tid  = threadIdx.x;
    const int lane = tid & 31, warp = tid >> 5;
    const int warpM = warp >> 2, warpN = warp & 3;   // 4 x 4
    const int g = lane >> 2, t = lane & 3;
    const int col0 = blockIdx.x * 128;

    for (int i = tid; i < 768; i += 512)
        atts[i] = att[2 * blockIdx.x * 384 + i];

    // ---- load resident B slice once ----
#pragma unroll
    for (int i = 0; i < 16; i++) {
        int s  = tid + i * 512;
        int n  = s >> 6;
        int ks = s & 63;
        cp16(smem_u32p(&Bres[n * 260 + ks * 4]),
             g_Wp_h + (size_t)(col0 + n) * 512 + ks * 8);
    }
    CP_COMMIT();
    CP_WAIT0();
    __syncthreads();

    // ldmatrix per-lane row-terms (u32 units)
    const int q8 = lane >> 3, r8 = lane & 7;
    uint32_t a_rt[3], b_rt[2];
#pragma unroll
    for (int mf = 0; mf < 3; mf++)
        a_rt[mf] = (uint32_t)((warpM * 48 + mf * 16 + r8 + (q8 & 1) * 8) * 36
                              + (q8 >> 1) * 4);
#pragma unroll
    for (int p = 0; p < 2; p++) {
        int nf = p * 2 + (q8 >> 1);
        b_rt[p] = (uint32_t)((warpN * 32 + nf * 8 + r8) * 260 + (q8 & 1) * 4);
    }
    const uint32_t As_b   = smem_u32p(As);
    const uint32_t Bres_b = smem_u32p(Bres);

    // A staging indices: 192 rows x 16 float4/row = 3072 slots, 6 per thread
    int arr[6], acc4[6];
#pragma unroll
    for (int i = 0; i < 6; i++) {
        int idx = tid + i * 512;
        arr[i]  = idx >> 4;
        acc4[i] = (idx & 15) * 4;
    }

    for (int tile = blockIdx.y; tile < K1_TILES; tile += gridDim.y) {
        const long row0 = (long)tile * 192;
        const int node0 = tile * 32;

        float acc[3][4][4];
#pragma unroll
        for (int mf = 0; mf < 3; mf++)
#pragma unroll
            for (int nf = 0; nf < 4; nf++)
#pragma unroll
                for (int v = 0; v < 4; v++) acc[mf][nf][v] = 0.f;

        float4 a_reg[6];
#pragma unroll
        for (int i = 0; i < 6; i++)
            a_reg[i] = *(const float4*)(x + (row0 + arr[i]) * 512 + acc4[i]);
#pragma unroll
        for (int i = 0; i < 6; i++) {
            uint32_t* d = As + arr[i] * 36 + (acc4[i] >> 1);
            *(uint2*)d = make_uint2(f2h2(a_reg[i].x, a_reg[i].y),
                                    f2h2(a_reg[i].z, a_reg[i].w));
        }
        __syncthreads();

        for (int it = 0; it < 8; it++) {
            const int buf = it & 1;
            if (it < 7) {
                const int ks = (it + 1) * 64;
#pragma unroll
                for (int i = 0; i < 6; i++)
                    a_reg[i] = *(const float4*)(x + (row0 + arr[i]) * 512
                                                + ks + acc4[i]);
            }
            // 4 k16 groups, per-warp rotated, ldmatrix fragment loads
#pragma unroll
            for (int gi = 0; gi < 4; gi++) {
                const int grp = (gi + warp) & 3;
                const uint32_t abase = As_b + (buf * 6912 + grp * 8) * 4;
                const uint32_t bbase = Bres_b + (it * 32 + grp * 8) * 4;
                uint32_t af[3][4], bf[2][4];
#pragma unroll
                for (int mf = 0; mf < 3; mf++)
                    ldsm4(af[mf][0], af[mf][1], af[mf][2], af[mf][3],
                          abase + a_rt[mf] * 4);
#pragma unroll
                for (int p = 0; p < 2; p++)
                    ldsm4(bf[p][0], bf[p][1], bf[p][2], bf[p][3],
                          bbase + b_rt[p] * 4);
#pragma unroll
                for (int mf = 0; mf < 3; mf++)
#pragma unroll
                    for (int p = 0; p < 2; p++) {
                        mma16(acc[mf][p * 2],     af[mf], &bf[p][0]);
                        mma16(acc[mf][p * 2 + 1], af[mf], &bf[p][2]);
                    }
            }
            if (it < 7) {
                uint32_t* An = As + (buf ^ 1) * 6912;
#pragma unroll
                for (int i = 0; i < 6; i++) {
                    uint32_t* d = An + arr[i] * 36 + (acc4[i] >> 1);
                    *(uint2*)d = make_uint2(f2h2(a_reg[i].x, a_reg[i].y),
                                            f2h2(a_reg[i].z, a_reg[i].w));
                }
            }
            __syncthreads();
        }

        // epilogue: two 64-col halves; Cs [192][68] reuses A region
        float* Cs = (float*)As;
#pragma unroll
        for (int half = 0; half < 2; half++) {
            if ((warpN >> 1) == half) {
#pragma unroll
                for (int mf = 0; mf < 3; mf++)
#pragma unroll
                    for (int nf = 0; nf < 4; nf++) {
                        const int r  = warpM * 48 + mf * 16 + g;
                        const int cc = (warpN & 1) * 32 + nf * 8 + t * 2;
                        Cs[r * 68 + cc]           = acc[mf][nf][0];
                        Cs[r * 68 + cc + 1]       = acc[mf][nf][1];
                        Cs[(r + 8) * 68 + cc]     = acc[mf][nf][2];
                        Cs[(r + 8) * 68 + cc + 1] = acc[mf][nf][3];
                    }
            }
            __syncthreads();
            {
                const int ty = tid >> 4;
                const int tx = tid & 15;
                const int node = node0 + ty;
                const int cg = half * 64 + tx * 4;
                float4 b4 = *(const float4*)(bp + col0 + cg);
                float bv[4] = {b4.x, b4.y, b4.z, b4.w};
                float zr[4];
#pragma unroll
                for (int c = 0; c < 4; c++) {
                    float h[NHOPS], am[NHOPS], s[NHOPS];
#pragma unroll
                    for (int r = 0; r < NHOPS; r++) {
                        float v = Cs[(ty * 6 + r) * 68 + tx * 4 + c] + bv[c];
                        v = v > 0.f ? v : NEG_ * v;
                        h[r]  = v;
                        am[r] = v * atts[half * 384 + r * 64 + tx * 4 + c];
                    }
                    float m = -1e30f;
#pragma unroll
                    for (int r = 0; r < NHOPS; r++) {
                        float u = am[0] + am[r];
                        u = u > 0.f ? u : NEG_ * u;
                        s[r] = u;
                        m = fmaxf(m, u);
                    }
                    float den = 0.f, num = 0.f;
#pragma unroll
                    for (int r = 0; r < NHOPS; r++) {
                        float w = expf(s[r] - m);
                        den += w;
                        num += h[r] * w;
                    }
                    zr[c] = num / den;
                }
                *(float4*)&g_z1[(long)node * 512 + col0 + cg] =
                    make_float4(zr[0], zr[1], zr[2], zr[3]);
            }
            __syncthreads();
        }
    }
}

// ---------------------------------------------------------------------------
// K2 (fp16 m16n8k16, unchanged): z = lrelu(z1 @ W_post^T + b) + zsq/zn.
// ---------------------------------------------------------------------------
__global__ void __launch_bounds__(512) smn_k2_tc(
    const float* __restrict__ bq, float* __restrict__ dout)
{
    extern __shared__ uint32_t dynsmem[];
    uint32_t* As = dynsmem;                   // 2 * 128*20
    uint32_t* Bs = As + 2 * 128 * 20;         // 2 * 256*20
    __shared__ float bias_s[256];

    const int tid  = threadIdx.x;
    const int lane = tid & 31, warp = tid >> 5;
    const int warpM = warp >> 2, warpN = warp & 3;
    const int g = lane >> 2, t = lane & 3;
    const long row0 = (long)blockIdx.x * 128;

    if (tid < 256) bias_s[tid] = bq[tid];

    const int ar[2] = { (tid + 0) >> 3, (tid + 512) >> 3 };
    const int ac    = (tid & 7) * 4;
    const int au    = ac >> 1;
    float4 a_reg[2];

    uint32_t bsa[2];
    const __half* wsrc[2];
#pragma unroll
    for (int i = 0; i < 2; i++) {
        int idx = tid + i * 512;
        int n   = idx >> 2;
        int kh  = (idx & 3) * 8;
        bsa[i]  = smem_u32p(&Bs[n * 20 + (kh >> 1)]);
        wsrc[i] = g_Wq_h + (long)n * 512 + kh;
    }
    const uint32_t bufB_bytes = 5120 * 4;

    float acc[2][8][4];
#pragma unroll
    for (int mf = 0; mf < 2; mf++)
#pragma unroll
        for (int nf = 0; nf < 8; nf++)
#pragma unroll
            for (int v = 0; v < 4; v++) acc[mf][nf][v] = 0.f;

#pragma unroll
    for (int i = 0; i < 2; i++) cp16(bsa[i], wsrc[i]);
    CP_COMMIT();
#pragma unroll
    for (int i = 0; i < 2; i++)
        a_reg[i] = *(const float4*)(g_z1 + (row0 + ar[i]) * 512 + ac);
#pragma unroll
    for (int i = 0; i < 2; i++) {
        uint32_t* d = As + ar[i] * 20 + au;
        *(uint2*)d = make_uint2(f2h2(a_reg[i].x, a_reg[i].y),
                                f2h2(a_reg[i].z, a_reg[i].w));
    }
    CP_WAIT0();
    __syncthreads();

    for (int it = 0; it < 16; it++) {
        const int buf = it & 1;
        if (it < 15) {
            const int ks = (it + 1) * 32;
#pragma unroll
            for (int i = 0; i < 2; i++)
                cp16(bsa[i] + (buf ^ 1) * bufB_bytes, wsrc[i] + ks);
            CP_COMMIT();
#pragma unroll
            for (int i = 0; i < 2; i++)
                a_reg[i] = *(const float4*)(g_z1 + (row0 + ar[i]) * 512 + ks + ac);
        }
        const uint32_t* Ab = As + buf * 2560;
        const uint32_t* Bb = Bs + buf * 5120;
#pragma unroll
        for (int gi = 0; gi < 2; gi++) {
            const int grp = (gi + warp) & 1;
            const int k8u = grp * 8;
            uint32_t af[2][4], bf[8][2];
#pragma unroll
            for (int mf = 0; mf < 2; mf++) {
                const int rb = warpM * 32 + mf * 16;
                af[mf][0] = Ab[(rb + g)     * 20 + k8u + t];
                af[mf][1] = Ab[(rb + g + 8) * 20 + k8u + t];
                af[mf][2] = Ab[(rb + g)     * 20 + k8u + t + 4];
                af[mf][3] = Ab[(rb + g + 8) * 20 + k8u + t + 4];
            }
#pragma unroll
            for (int nf = 0; nf < 8; nf++) {
                const int nb = warpN * 64 + nf * 8;
                bf[nf][0] = Bb[(nb + g) * 20 + k8u + t];
                bf[nf][1] = Bb[(nb + g) * 20 + k8u + t + 4];
            }
#pragma unroll
            for (int mf = 0; mf < 2; mf++)
#pragma unroll
                for (int nf = 0; nf < 8; nf++)
                    mma16(acc[mf][nf], af[mf], bf[nf]);
        }
        if (it < 15) {
            uint32_t* An = As + (buf ^ 1) * 2560;
#pragma unroll
            for (int i = 0; i < 2; i++) {
                uint32_t* d = An + ar[i] * 20 + au;
                *(uint2*)d = make_uint2(f2h2(a_reg[i].x, a_reg[i].y),
                                        f2h2(a_reg[i].z, a_reg[i].w));
            }
            CP_WAIT0();
        }
        __syncthreads();
    }

    float* part = (float*)As;     // [128][4]
    float zp[4] = {0.f, 0.f, 0.f, 0.f};
#pragma unroll
    for (int mf = 0; mf < 2; mf++) {
#pragma unroll
        for (int nf = 0; nf < 8; nf++) {
            const int rl  = warpM * 32 + mf * 16 + g;
            const int col = warpN * 64 + nf * 8 + t * 2;
            float v0 = acc[mf][nf][0] + bias_s[col];
            float v1 = acc[mf][nf][1] + bias_s[col + 1];
            float v2 = acc[mf][nf][2] + bias_s[col];
            float v3 = acc[mf][nf][3] + bias_s[col + 1];
            v0 = v0 > 0.f ? v0 : NEG_ * v0;
            v1 = v1 > 0.f ? v1 : NEG_ * v1;
            v2 = v2 > 0.f ? v2 : NEG_ * v2;
            v3 = v3 > 0.f ? v3 : NEG_ * v3;
            *(float2*)&dout[Z_OFF + (row0 + rl) * 256 + col] =
                make_float2(v0, v1);
            *(float2*)&dout[Z_OFF + (row0 + rl + 8) * 256 + col] =
                make_float2(v2, v3);
            zp[mf * 2]     += v0 * v0 + v1 * v1;
            zp[mf * 2 + 1] += v2 * v2 + v3 * v3;
        }
    }
#pragma unroll
    for (int j = 0; j < 4; j++) {
        zp[j] += __shfl_xor_sync(0xffffffffu, zp[j], 1);
        zp[j] += __shfl_xor_sync(0xffffffffu, zp[j], 2);
    }
    __syncthreads();
    if (t == 0) {
#pragma unroll
        for (int j = 0; j < 4; j++) {
            const int rl = warpM * 32 + (j >> 1) * 16 + g + (j & 1) * 8;
            part[rl * 4 + warpN] = zp[j];
        }
    }
    __syncthreads();
    if (tid < 128) {
        float s = part[tid * 4] + part[tid * 4 + 1]
                + part[tid * 4 + 2] + part[tid * 4 + 3];
        g_zsq[row0 + tid] = s;
        g_zn[row0 + tid]  = fmaxf(sqrtf(s), COS_EPS_);
    }
}

// ---------------------------------------------------------------------------
// K3 (tf32 mma, unchanged, ~24us)
// ---------------------------------------------------------------------------
__global__ void __launch_bounds__(256) smn_k3_tc(float* __restrict__ dout)
{
    extern __shared__ uint32_t dynsmem[];
    uint32_t* Bs = dynsmem;
    uint32_t* As = dynsmem + 10240;
    __shared__ float csq_s[NCLASS_], cn_s[NCLASS_];

    const int tid  = threadIdx.x;
    const int lane = tid & 31, warp = tid >> 5;
    const int g = lane >> 2, t = lane & 3;
    const long row0 = (long)blockIdx.x * 128;
    const float* zg = dout + Z_OFF;

    for (int e = tid; e < NSSF_ * NCLASS_; e += 256) {
        int k = e / NCLASS_, n = e - k * NCLASS_;
        float v = dout[SSFN_OFF + e];
        int kk = k >> 3, kp = k & 7, tt = kp & 3, hi2 = kp >> 2;
        int phys = (((n & 7) * 4 + tt) + kk * 2) & 31;
        Bs[((n >> 3) * 32 + kk) * 64 + phys * 2 + hi2] = f2tf(v);
    }
    if (tid < NCLASS_) { csq_s[tid] = g_csq[tid]; cn_s[tid] = g_cn[tid]; }

    const int ar[4] = { (tid) >> 3, (tid + 256) >> 3,
                        (tid + 512) >> 3, (tid + 768) >> 3 };
    const int ac  = (tid & 7) * 4;
    const int kkt = ac >> 3, hit = (ac >> 2) & 1, rot = kkt * 2;
    float4 a_reg[4];

    auto stageA3 = [&](uint32_t* dstbuf) {
#pragma unroll
        for (int i = 0; i < 4; i++) {
            const int r = ar[i];
            uint32_t* d = dstbuf + (((r >> 4) * 4 + kkt) * 128)
                        + ((r >> 3) & 1) + 2 * hit;
            const int l0 = (r & 7) * 4;
            d[(((l0 + 0) + rot) & 31) * 4] = f2tf(a_reg[i].x);
            d[(((l0 + 1) + rot) & 31) * 4] = f2tf(a_reg[i].y);
            d[(((l0 + 2) + rot) & 31) * 4] = f2tf(a_reg[i].z);
            d[(((l0 + 3) + rot) & 31) * 4] = f2tf(a_reg[i].w);
        }
    };

    float acc[5][4];
#pragma unroll
    for (int nf = 0; nf < 5; nf++)
#pragma unroll
        for (int v = 0; v < 4; v++) acc[nf][v] = 0.f;

#pragma unroll
    for (int i = 0; i < 4; i++)
        a_reg[i] = *(const float4*)(zg + (row0 + ar[i]) * 256 + ac);
    stageA3(As);
    __syncthreads();

    for (int it = 0; it < 8; it++) {
        const int buf = it & 1;
        if (it < 7) {
            const int ks = (it + 1) * 32;
#pragma unroll
            for (int i = 0; i < 4; i++)
                a_reg[i] = *(const float4*)(zg + (row0 + ar[i]) * 256 + ks + ac);
        }
        const uint32_t* Ab = As + buf * 4096;
#pragma unroll
        for (int kk = 0; kk < 4; kk++) {
            const int kkg = it * 4 + kk;
            const int prA = (lane + kk * 2) & 31;
            const int prB = (lane + kkg * 2) & 31;
            uint4 av = *(const uint4*)&Ab[(warp * 4 + kk) * 128 + prA * 4];
#pragma unroll
            for (int nf = 0; nf < 5; nf++) {
                uint2 bv = *(const uint2*)&Bs[(nf * 32 + kkg) * 64 + prB * 2];
                mma8(acc[nf], reinterpret_cast<const uint32_t*>(&av),
                     reinterpret_cast<const uint32_t*>(&bv));
            }
        }
        if (it < 7) stageA3(As + (buf ^ 1) * 4096);
        __syncthreads();
    }

#pragma unroll
    for (int rs = 0; rs < 2; rs++) {
        const long row = row0 + warp * 16 + g + rs * 8;
        const float zsq = g_zsq[row];
        const float zn  = g_zn[row];
        float dv[5][2], sv[5][2], av[5][2];
        float md = -1e30f, ms = -1e30f;
#pragma unroll
        for (int nf = 0; nf < 5; nf++) {
#pragma unroll
            for (int u = 0; u < 2; u++) {
                const int col = nf * 8 + t * 2 + u;
                float a = acc[nf][rs * 2 + u];
                av[nf][u] = a;
                float d = -sqrtf(fmaxf(zsq + csq_s[col] - 2.f * a, 0.f));
                float s = a / (zn * cn_s[col]);
                dv[nf][u] = d; sv[nf][u] = s;
                md = fmaxf(md, d); ms = fmaxf(ms, s);
            }
        }
        md = fmaxf(md, __shfl_xor_sync(0xffffffffu, md, 1));
        md = fmaxf(md, __shfl_xor_sync(0xffffffffu, md, 2));
        ms = fmaxf(ms, __shfl_xor_sync(0xffffffffu, ms, 1));
        ms = fmaxf(ms, __shfl_xor_sync(0xffffffffu, ms, 2));
        float ed = 0.f, es = 0.f;
#pragma unroll
        for (int nf = 0; nf < 5; nf++)
#pragma unroll
            for (int u = 0; u < 2; u++) {
                ed += expf(dv[nf][u] - md);
                es += expf(sv[nf][u] - ms);
            }
        ed += __shfl_xor_sync(0xffffffffu, ed, 1);
        ed += __shfl_xor_sync(0xffffffffu, ed, 2);
        es += __shfl_xor_sync(0xffffffffu, es, 1);
        es += __shfl_xor_sync(0xffffffffu, es, 2);
        const float lse_d = md + logf(ed);
        const float lse_s = ms + logf(es);
#pragma unroll
        for (int nf = 0; nf < 5; nf++) {
            const int col = nf * 8 + t * 2;
            *(float2*)&dout[OUT_OFF + row * NCLASS_ + col] =
                make_float2(av[nf][0], av[nf][1]);
            *(float2*)&dout[LOSS_OFF + row * NCLASS_ + col] = make_float2(
                0.5f * ((dv[nf][0] - lse_d) + (sv[nf][0] - lse_s)),
                0.5f * ((dv[nf][1] - lse_d) + (sv[nf][1] - lse_s)));
        }
    }
}

// ---------------------------------------------------------------------------
extern "C" void kernel_launch(void* const* d_in, const int* in_sizes, int n_in,
                              void* d_out, int out_size)
{
    const float* x      = (const float*)d_in[0];
    const float* W_pre  = (const float*)d_in[1];
    const float* b_pre  = (const float*)d_in[2];
    const float* att    = (const float*)d_in[3];
    const float* W_post = (const float*)d_in[4];
    const float* b_post = (const float*)d_in[5];
    const float* ssf    = (const float*)d_in[6];
    const float* sigma  = (const float*)d_in[7];
    float* dout = (float*)d_out;

    const int K1_SMEM = (768 + 128 * 260 + 2 * 192 * 36) * 4;    // 191488
    const int K2_SMEM = (2 * 128 * 20 + 2 * 256 * 20) * 4;       // 61440
    const int K3_SMEM = (10240 + 2 * 4096) * 4;                  // 73728
    cudaFuncSetAttribute(smn_k1_tc,
                         cudaFuncAttributeMaxDynamicSharedMemorySize, K1_SMEM);
    cudaFuncSetAttribute(smn_k2_tc,
                         cudaFuncAttributeMaxDynamicSharedMemorySize, K2_SMEM);
    cudaFuncSetAttribute(smn_k3_tc,
                         cudaFuncAttributeMaxDynamicSharedMemorySize, K3_SMEM);

    smn_wcvt_ssf<<<1537, 256>>>(W_pre, W_post, ssf, sigma, dout);
    smn_k1_tc<<<dim3(4, 148), 512, K1_SMEM>>>(x, b_pre, att);
    smn_k2_tc<<<NN / 128, 512, K2_SMEM>>>(b_post, dout);
    smn_k3_tc<<<NN / 128, 256, K3_SMEM>>>(dout);
}